// round 4
// baseline (speedup 1.0000x reference)
#include <cuda_runtime.h>
#include <cuda_bf16.h>
#include <math.h>
#include <stdint.h>

#define B_    8
#define T_    12
#define NN_   883
#define DM    152
#define DD2   304
#define SSZ   128
#define NL    3
#define STEPS 288
#define ROWS  (B_*NN_)          /* 7064  */
#define MTOK  (ROWS*T_)         /* 84768 */
#define MBLK  ((MTOK+63)/64)    /* 1325  */

// ---------------- scratch (device globals; no allocs allowed) ----------------
__device__ float g_h [MTOK*DM];
__device__ float g_xp[MTOK*DD2];
__device__ float g_BC[MTOK*256];
__device__ float g_z [MTOK*DD2];
__device__ float g_s [MTOK];

__device__ __nv_bfloat16 g_xn_h [MTOK*DM],  g_xn_l [MTOK*DM];
__device__ __nv_bfloat16 g_xca_h[MTOK*DD2], g_xca_l[MTOK*DD2];
__device__ __nv_bfloat16 g_xco_h[MTOK*DD2], g_xco_l[MTOK*DD2];
__device__ __nv_bfloat16 g_cb_h [MTOK*DD2], g_cb_l [MTOK*DD2];

// split + transposed weights: [N rows, K cols] bf16
__device__ __nv_bfloat16 g_wip_h[NL*DD2*DM],  g_wip_l[NL*DD2*DM];
__device__ __nv_bfloat16 g_wcl_h[NL*DD2*DD2], g_wcl_l[NL*DD2*DD2];
__device__ __nv_bfloat16 g_w23_h[NL*256*DD2], g_w23_l[NL*256*DD2];
__device__ __nv_bfloat16 g_wf1_h[NL*DD2*DD2], g_wf1_l[NL*DD2*DD2];
__device__ __nv_bfloat16 g_wdw_h[NL*DD2*DM],  g_wdw_l[NL*DD2*DM];
__device__ __nv_bfloat16 g_wop_h[NL*DM*DD2],  g_wop_l[NL*DM*DD2];
__device__ float g_b23[NL*256];

__device__ __forceinline__ float siluf(float v)     { return v / (1.f + expf(-v)); }
__device__ __forceinline__ float softplusf(float v) { return (v > 20.f) ? v : log1pf(expf(v)); }

__device__ __forceinline__ uint32_t sm2u32(const void* p) {
    uint32_t a;
    asm("{ .reg .u64 t; cvta.to.shared.u64 t, %1; cvt.u32.u64 %0, t; }" : "=r"(a) : "l"(p));
    return a;
}
#define SWZ(o) ((uint32_t)(o) ^ ((((uint32_t)(o)) >> 3) & 0x70u))

__device__ __forceinline__ void ldsm4(uint32_t* r, uint32_t addr) {
    asm volatile("ldmatrix.sync.aligned.m8n8.x4.shared.b16 {%0,%1,%2,%3}, [%4];"
                 : "=r"(r[0]), "=r"(r[1]), "=r"(r[2]), "=r"(r[3]) : "r"(addr));
}
__device__ __forceinline__ void mma16816(float* c, const uint32_t* a, const uint32_t* b) {
    asm volatile("mma.sync.aligned.m16n8k16.row.col.f32.bf16.bf16.f32 "
                 "{%0,%1,%2,%3}, {%4,%5,%6,%7}, {%8,%9}, {%0,%1,%2,%3};"
                 : "+f"(c[0]), "+f"(c[1]), "+f"(c[2]), "+f"(c[3])
                 : "r"(a[0]), "r"(a[1]), "r"(a[2]), "r"(a[3]), "r"(b[0]), "r"(b[1]));
}
__device__ __forceinline__ void cpa16(uint32_t dst, const void* src, uint32_t sz) {
    asm volatile("cp.async.cg.shared.global [%0], [%1], 16, %2;"
                 :: "r"(dst), "l"(src), "r"(sz) : "memory");
}
__device__ __forceinline__ void cp_commit() {
    asm volatile("cp.async.commit_group;" ::: "memory");
}
template<int N>
__device__ __forceinline__ void cp_wait() {
    asm volatile("cp.async.wait_group %0;" :: "n"(N) : "memory");
}

// ---------------- fused epilogue -------------------------------------------
// EPI: 0 bias->f32, 1 silu->f32, 3 bias->split bf16, 4 fc1+combine->split bf16
template<int EPI>
__device__ __forceinline__ void epi2(int m, int col, int ldc, float v0, float v1,
    const float* __restrict__ bias, float* Cf, __nv_bfloat16* Ch, __nv_bfloat16* Cl)
{
    v0 += bias[col]; v1 += bias[col + 1];
    if (EPI == 1) { v0 = siluf(v0); v1 = siluf(v1); }
    if (EPI == 4) {
        float sv = g_s[m];
        size_t off = (size_t)m * DD2 + col;
        float xc0 = __bfloat162float(g_xco_h[off])   + __bfloat162float(g_xco_l[off]);
        float xc1 = __bfloat162float(g_xco_h[off+1]) + __bfloat162float(g_xco_l[off+1]);
        v0 = siluf(xc0 * softplusf(v0) * sv) * g_z[off];
        v1 = siluf(xc1 * softplusf(v1) * sv) * g_z[off + 1];
    }
    if (EPI == 0 || EPI == 1) {
        *(float2*)(Cf + (size_t)m * ldc + col) = make_float2(v0, v1);
    } else {
        __nv_bfloat16 h0 = __float2bfloat16(v0), h1 = __float2bfloat16(v1);
        __nv_bfloat16 l0 = __float2bfloat16(v0 - __bfloat162float(h0));
        __nv_bfloat16 l1 = __float2bfloat16(v1 - __bfloat162float(h1));
        *(__nv_bfloat162*)(Ch + (size_t)m * ldc + col) = __halves2bfloat162(h0, h1);
        *(__nv_bfloat162*)(Cl + (size_t)m * ldc + col) = __halves2bfloat162(l0, l1);
    }
}

// ---------------- GEMM: C[M,Nw] = epi(A[M,K] @ B[Nw,K]^T + bias) -------------
// CTA tile 64(M) x 256(N), K-chunk 64, 2-stage cp.async pipeline.
// 8 warps: wm = wid>>2 (2 along M, 32 rows), wn = wid&3 (4 along N, 64 cols).
#define STG_AH 0
#define STG_AL 8192
#define STG_BH 16384
#define STG_BL 49152
#define STG_SZ 81920
#define SMEM_TOTAL (2*STG_SZ)

template<int EPI>
__global__ void __launch_bounds__(256, 1)
mma_gemm(const __nv_bfloat16* __restrict__ Ah, const __nv_bfloat16* __restrict__ Al,
         const __nv_bfloat16* __restrict__ Bh, const __nv_bfloat16* __restrict__ Bl,
         const float* __restrict__ bias,
         float* Cf, __nv_bfloat16* Ch, __nv_bfloat16* Cl,
         int M, int K, int Nw, int ldc)
{
    extern __shared__ char smem[];
    const uint32_t sb = sm2u32(smem);
    const int tid  = threadIdx.x;
    const int lane = tid & 31;
    const int wid  = tid >> 5;
    const int wm   = wid >> 2;     // 0..1
    const int wn   = wid & 3;      // 0..3
    const int m0   = blockIdx.y * 64;
    const int n0   = blockIdx.x * 256;

    float acc[2][8][4];
#pragma unroll
    for (int i = 0; i < 2; i++)
#pragma unroll
        for (int j = 0; j < 8; j++)
#pragma unroll
            for (int q = 0; q < 4; q++) acc[i][j][q] = 0.f;

    const int KC = (K + 63) >> 6;

    auto load_stage = [&](int stg, int k0) {
        uint32_t base = sb + stg * STG_SZ;
        // A: 64 rows x 64 k (hi & lo)
#pragma unroll
        for (int i = 0; i < 2; i++) {
            int idx = tid + i * 256;
            int r = idx >> 3, u = idx & 7;
            int gm = m0 + r, gk = k0 + u * 8;
            bool ok = (gm < M) && (gk < K);
            size_t go = (size_t)(ok ? gm : 0) * K + (ok ? gk : 0);
            uint32_t sz = ok ? 16u : 0u;
            uint32_t o = SWZ(r * 128 + u * 16);
            cpa16(base + STG_AH + o, Ah + go, sz);
            cpa16(base + STG_AL + o, Al + go, sz);
        }
        // B: 256 rows x 64 k (hi & lo)
#pragma unroll
        for (int i = 0; i < 8; i++) {
            int idx = tid + i * 256;
            int r = idx >> 3, u = idx & 7;
            int gn = n0 + r, gk = k0 + u * 8;
            bool ok = (gn < Nw) && (gk < K);
            size_t go = (size_t)(ok ? gn : 0) * K + (ok ? gk : 0);
            uint32_t sz = ok ? 16u : 0u;
            uint32_t o = SWZ(r * 128 + u * 16);
            cpa16(base + STG_BH + o, Bh + go, sz);
            cpa16(base + STG_BL + o, Bl + go, sz);
        }
    };

    load_stage(0, 0);
    cp_commit();

    for (int c = 0; c < KC; c++) {
        if (c + 1 < KC) {
            load_stage((c + 1) & 1, (c + 1) << 6);
            cp_commit();
            cp_wait<1>();
        } else {
            cp_wait<0>();
        }
        __syncthreads();

        const uint32_t base = sb + (c & 1) * STG_SZ;
#pragma unroll
        for (int ks = 0; ks < 4; ks++) {
            const int kb = ks * 16;
            uint32_t ah[2][4], al[2][4];
#pragma unroll
            for (int mt = 0; mt < 2; mt++) {
                int row = wm * 32 + mt * 16 + (lane & 15);
                uint32_t o = SWZ(row * 128 + (kb + (lane >> 4) * 8) * 2);
                ldsm4(ah[mt], base + STG_AH + o);
                ldsm4(al[mt], base + STG_AL + o);
            }
            uint32_t bh[8][2], bl[8][2];
            {
                int q = lane >> 3;
                int rowo = (q >> 1) * 8 + (lane & 7);
                int ko   = (q & 1) * 8;
#pragma unroll
                for (int p = 0; p < 4; p++) {
                    int row = wn * 64 + p * 16 + rowo;
                    uint32_t o = SWZ(row * 128 + (kb + ko) * 2);
                    uint32_t r4[4];
                    ldsm4(r4, base + STG_BH + o);
                    bh[p*2][0] = r4[0]; bh[p*2][1] = r4[1];
                    bh[p*2+1][0] = r4[2]; bh[p*2+1][1] = r4[3];
                    ldsm4(r4, base + STG_BL + o);
                    bl[p*2][0] = r4[0]; bl[p*2][1] = r4[1];
                    bl[p*2+1][0] = r4[2]; bl[p*2+1][1] = r4[3];
                }
            }
#pragma unroll
            for (int mt = 0; mt < 2; mt++)
#pragma unroll
                for (int nt = 0; nt < 8; nt++) {
                    mma16816(acc[mt][nt], ah[mt], bh[nt]);
                    mma16816(acc[mt][nt], ah[mt], bl[nt]);
                    mma16816(acc[mt][nt], al[mt], bh[nt]);
                }
        }
        __syncthreads();
    }

    // ---- epilogue ----
#pragma unroll
    for (int mt = 0; mt < 2; mt++) {
        int r0 = m0 + wm * 32 + mt * 16 + (lane >> 2);
        int r1 = r0 + 8;
#pragma unroll
        for (int nt = 0; nt < 8; nt++) {
            int col = n0 + wn * 64 + nt * 8 + (lane & 3) * 2;
            if (col < Nw) {
                if (r0 < M) epi2<EPI>(r0, col, ldc, acc[mt][nt][0], acc[mt][nt][1], bias, Cf, Ch, Cl);
                if (r1 < M) epi2<EPI>(r1, col, ldc, acc[mt][nt][2], acc[mt][nt][3], bias, Cf, Ch, Cl);
            }
        }
    }
}

// ---------------- weight transpose + split: W[K,N] -> Bt[N,K] hi/lo ----------
__global__ void wsplit(const float* __restrict__ W, __nv_bfloat16* __restrict__ oh,
                       __nv_bfloat16* __restrict__ ol, int K, int N)
{
    int idx = blockIdx.x * blockDim.x + threadIdx.x;
    if (idx >= K * N) return;
    int n = idx / K, k = idx % K;
    float v = W[(size_t)k * N + n];
    __nv_bfloat16 h = __float2bfloat16(v);
    oh[idx] = h;
    ol[idx] = __float2bfloat16(v - __bfloat162float(h));
}

__global__ void pack_b23(const float* __restrict__ b2, const float* __restrict__ b3,
                         float* __restrict__ dst)
{
    int i = threadIdx.x;
    dst[i] = (i < 128) ? b2[i] : b3[i - 128];
}

// ---------------- embedding ----------------
__global__ void embed_kernel(const float* __restrict__ x, const float* __restrict__ W_in,
                             const float* __restrict__ b_in, const float* __restrict__ tod,
                             const float* __restrict__ dow, const float* __restrict__ adp)
{
    long idx = blockIdx.x * (long)blockDim.x + threadIdx.x;
    if (idx >= (long)MTOK * DM) return;
    int  c      = (int)(idx % DM);
    long tokidx = idx / DM;
    int  t      = (int)(tokidx % T_);
    long rn     = tokidx / T_;
    int  n      = (int)(rn % NN_);
    int  b      = (int)(rn / NN_);
    const float* xe = x + (((long)(b * T_ + t) * NN_ + n) * 3);
    float v;
    if (c < 24) {
        v = b_in[c] + xe[0]*W_in[c] + xe[1]*W_in[24+c] + xe[2]*W_in[48+c];
    } else if (c < 48) {
        int ti = (int)(xe[1] * (float)STEPS);
        ti = min(max(ti, 0), STEPS - 1);
        v = tod[ti*24 + (c-24)];
    } else if (c < 72) {
        int di = (int)xe[2];
        di = min(max(di, 0), 6);
        v = dow[di*24 + (c-48)];
    } else {
        v = adp[((long)t * NN_ + n) * 80 + (c - 72)];
    }
    g_h[idx] = v;
}

// ---------------- rmsnorm -> split bf16 ----------------
__global__ void rmsnorm_kernel(const float* __restrict__ w)
{
    int gwarp = (blockIdx.x * blockDim.x + threadIdx.x) >> 5;
    int lane  = threadIdx.x & 31;
    if (gwarp >= MTOK) return;
    const float* row = g_h + (long)gwarp * DM;
    float ss = 0.f;
    for (int c = lane; c < DM; c += 32) { float v = row[c]; ss += v * v; }
#pragma unroll
    for (int o = 16; o; o >>= 1) ss += __shfl_xor_sync(0xffffffffu, ss, o);
    float scale = rsqrtf(ss / (float)DM + 1e-5f);
    long base = (long)gwarp * DM;
    for (int c = lane; c < DM; c += 32) {
        float v = row[c] * scale * w[c];
        __nv_bfloat16 h = __float2bfloat16(v);
        g_xn_h[base + c] = h;
        g_xn_l[base + c] = __float2bfloat16(v - __bfloat162float(h));
    }
}

// ---------------- conv over T + silu -> split bf16 (shfl neighbors) ----------
__global__ void conv_silu_kernel(const float* __restrict__ cw, const float* __restrict__ cb)
{
    __shared__ float w[T_*T_*3];
    __shared__ float bsh[T_];
    for (int i = threadIdx.x; i < T_*T_*3; i += blockDim.x) w[i] = cw[i];
    for (int i = threadIdx.x; i < T_;      i += blockDim.x) bsh[i] = cb[i];
    __syncthreads();

    long idx = blockIdx.x * (long)blockDim.x + threadIdx.x;
    if (idx >= (long)ROWS * DD2) return;
    int  d = (int)(idx % DD2);
    long r = idx / DD2;
    int lane = threadIdx.x & 31;
    const float* xrow = g_xp + r * (long)(T_ * DD2);

    float v1[T_];
#pragma unroll
    for (int ti = 0; ti < T_; ti++) v1[ti] = xrow[ti*DD2 + d];

    float acc[T_];
#pragma unroll
    for (int to = 0; to < T_; to++) acc[to] = bsh[to];

#pragma unroll
    for (int ti = 0; ti < T_; ti++) {
        float v0 = __shfl_up_sync(0xffffffffu, v1[ti], 1);
        float v2 = __shfl_down_sync(0xffffffffu, v1[ti], 1);
        if (lane == 0)  v0 = (d > 0)       ? xrow[ti*DD2 + d - 1] : 0.f;
        if (lane == 31) v2 = (d < DD2 - 1) ? xrow[ti*DD2 + d + 1] : 0.f;
#pragma unroll
        for (int to = 0; to < T_; to++) {
            const float* wp = &w[(to*T_ + ti)*3];
            acc[to] += v0*wp[0] + v1[ti]*wp[1] + v2*wp[2];
        }
    }
    long obase = r * (long)(T_ * DD2) + d;
#pragma unroll
    for (int to = 0; to < T_; to++) {
        float v = siluf(acc[to]);
        __nv_bfloat16 h = __float2bfloat16(v);
        g_xca_h[obase + to*DD2] = h;
        g_xca_l[obase + to*DD2] = __float2bfloat16(v - __bfloat162float(h));
    }
}

// ---------------- s[token] = dot(BC[:,0:128], BC[:,128:256]) ----------------
__global__ void sdot_kernel()
{
    int gwarp = (blockIdx.x * blockDim.x + threadIdx.x) >> 5;
    int lane  = threadIdx.x & 31;
    if (gwarp >= MTOK) return;
    const float* row = g_BC + (long)gwarp * 256;
    float4 a = *(const float4*)(row + lane * 4);
    float4 b = *(const float4*)(row + 128 + lane * 4);
    float acc = a.x*b.x + a.y*b.y + a.z*b.z + a.w*b.w;
#pragma unroll
    for (int o = 16; o; o >>= 1) acc += __shfl_xor_sync(0xffffffffu, acc, o);
    if (!lane) g_s[gwarp] = acc;
}

// ---------------- head ----------------
__global__ void out_kernel(const float* __restrict__ Wout, const float* __restrict__ bout,
                           float* __restrict__ out)
{
    int rn   = blockIdx.x;
    int wj   = threadIdx.x >> 5;
    int lane = threadIdx.x & 31;
    const float* row = g_h + (long)rn * (T_ * DM);
    float acc = 0.f;
    for (int k = lane; k < T_ * DM; k += 32) acc += row[k] * Wout[k*12 + wj];
#pragma unroll
    for (int o = 16; o; o >>= 1) acc += __shfl_xor_sync(0xffffffffu, acc, o);
    if (!lane) {
        int n = rn % NN_, b = rn / NN_;
        out[((long)b * 12 + wj) * NN_ + n] = acc + bout[wj];
    }
}

// =============================================================================
extern "C" void kernel_launch(void* const* d_in, const int* in_sizes, int n_in,
                              void* d_out, int out_size)
{
    (void)in_sizes; (void)n_in; (void)out_size;
    const float* x        = (const float*)d_in[0];
    const float* W_in     = (const float*)d_in[1];
    const float* b_in     = (const float*)d_in[2];
    const float* tod      = (const float*)d_in[3];
    const float* dow      = (const float*)d_in[4];
    const float* adp      = (const float*)d_in[5];
    const float* norm_w   = (const float*)d_in[6];
    const float* inproj_w = (const float*)d_in[7];
    const float* inproj_b = (const float*)d_in[8];
    const float* conv_w   = (const float*)d_in[9];
    const float* conv_b   = (const float*)d_in[10];
    const float* convlin_w= (const float*)d_in[11];
    const float* convlin_b= (const float*)d_in[12];
    const float* fc1_w    = (const float*)d_in[13];
    const float* fc1_b    = (const float*)d_in[14];
    const float* fc2_w    = (const float*)d_in[15];
    const float* fc2_b    = (const float*)d_in[16];
    const float* fc3_w    = (const float*)d_in[17];
    const float* fc3_b    = (const float*)d_in[18];
    /* d_in[19] = A_ssm unused (h0 == 0) */
    const float* D_w      = (const float*)d_in[20];
    const float* D_b      = (const float*)d_in[21];
    const float* outproj_w= (const float*)d_in[22];
    const float* outproj_b= (const float*)d_in[23];
    const float* W_out    = (const float*)d_in[24];
    const float* b_out    = (const float*)d_in[25];
    float* out = (float*)d_out;

    cudaFuncSetAttribute(mma_gemm<0>, cudaFuncAttributeMaxDynamicSharedMemorySize, SMEM_TOTAL);
    cudaFuncSetAttribute(mma_gemm<1>, cudaFuncAttributeMaxDynamicSharedMemorySize, SMEM_TOTAL);
    cudaFuncSetAttribute(mma_gemm<3>, cudaFuncAttributeMaxDynamicSharedMemorySize, SMEM_TOTAL);
    cudaFuncSetAttribute(mma_gemm<4>, cudaFuncAttributeMaxDynamicSharedMemorySize, SMEM_TOTAL);

    void* p;
#define SYM(sym, var, ty) cudaGetSymbolAddress(&p, sym); ty* var = (ty*)p;
    SYM(g_xp,    xp_p,   float)
    SYM(g_BC,    BC_p,   float)
    SYM(g_z,     z_p,    float)
    SYM(g_b23,   b23_p,  float)
    SYM(g_h,     h_p,    float)
    SYM(g_xn_h,  xnh_p,  __nv_bfloat16)  SYM(g_xn_l,  xnl_p,  __nv_bfloat16)
    SYM(g_xca_h, xcah_p, __nv_bfloat16)  SYM(g_xca_l, xcal_p, __nv_bfloat16)
    SYM(g_xco_h, xcoh_p, __nv_bfloat16)  SYM(g_xco_l, xcol_p, __nv_bfloat16)
    SYM(g_cb_h,  cbh_p,  __nv_bfloat16)  SYM(g_cb_l,  cbl_p,  __nv_bfloat16)
    SYM(g_wip_h, wiph_p, __nv_bfloat16)  SYM(g_wip_l, wipl_p, __nv_bfloat16)
    SYM(g_wcl_h, wclh_p, __nv_bfloat16)  SYM(g_wcl_l, wcll_p, __nv_bfloat16)
    SYM(g_w23_h, w23h_p, __nv_bfloat16)  SYM(g_w23_l, w23l_p, __nv_bfloat16)
    SYM(g_wf1_h, wf1h_p, __nv_bfloat16)  SYM(g_wf1_l, wf1l_p, __nv_bfloat16)
    SYM(g_wdw_h, wdwh_p, __nv_bfloat16)  SYM(g_wdw_l, wdwl_p, __nv_bfloat16)
    SYM(g_wop_h, woph_p, __nv_bfloat16)  SYM(g_wop_l, wopl_p, __nv_bfloat16)
#undef SYM

    // ---- weight prep ----
    for (int i = 0; i < NL; i++) {
        wsplit<<<(DD2*DM + 255)/256, 256>>>(inproj_w + (long)i*DM*DD2,
            wiph_p + (long)i*DD2*DM, wipl_p + (long)i*DD2*DM, DM, DD2);
        wsplit<<<(DD2*DD2 + 255)/256, 256>>>(convlin_w + (long)i*DD2*DD2,
            wclh_p + (long)i*DD2*DD2, wcll_p + (long)i*DD2*DD2, DD2, DD2);
        wsplit<<<(SSZ*DD2 + 255)/256, 256>>>(fc2_w + (long)i*DD2*SSZ,
            w23h_p + (long)i*256*DD2,            w23l_p + (long)i*256*DD2, DD2, SSZ);
        wsplit<<<(SSZ*DD2 + 255)/256, 256>>>(fc3_w + (long)i*DD2*SSZ,
            w23h_p + (long)i*256*DD2 + 128*DD2,  w23l_p + (long)i*256*DD2 + 128*DD2, DD2, SSZ);
        wsplit<<<(DD2*DD2 + 255)/256, 256>>>(fc1_w + (long)i*DD2*DD2,
            wf1h_p + (long)i*DD2*DD2, wf1l_p + (long)i*DD2*DD2, DD2, DD2);
        wsplit<<<(DD2*DM + 255)/256, 256>>>(D_w + (long)i*DM*DD2,
            wdwh_p + (long)i*DD2*DM, wdwl_p + (long)i*DD2*DM, DM, DD2);
        wsplit<<<(DM*DD2 + 255)/256, 256>>>(outproj_w + (long)i*DD2*DM,
            woph_p + (long)i*DM*DD2, wopl_p + (long)i*DM*DD2, DD2, DM);
        pack_b23<<<1, 256>>>(fc2_b + i*SSZ, fc3_b + i*SSZ, b23_p + i*256);
    }

    // ---- embedding ----
    {
        long tot = (long)MTOK * DM;
        embed_kernel<<<(int)((tot + 255)/256), 256>>>(x, W_in, b_in, tod, dow, adp);
    }

    for (int i = 0; i < NL; i++) {
        rmsnorm_kernel<<<(MTOK*32 + 255)/256, 256>>>(norm_w + i*DM);

        // inproj: xn(152) -> xp(304) f32
        mma_gemm<0><<<dim3(2, MBLK), 256, SMEM_TOTAL>>>(xnh_p, xnl_p,
            wiph_p + (long)i*DD2*DM, wipl_p + (long)i*DD2*DM, inproj_b + i*DD2,
            xp_p, nullptr, nullptr, MTOK, DM, DD2, DD2);

        conv_silu_kernel<<<((long)ROWS*DD2 + 255)/256, 256>>>(conv_w + i*T_*T_*3, conv_b + i*T_);

        // convlin: xca(304) -> xco split(304)
        mma_gemm<3><<<dim3(2, MBLK), 256, SMEM_TOTAL>>>(xcah_p, xcal_p,
            wclh_p + (long)i*DD2*DD2, wcll_p + (long)i*DD2*DD2, convlin_b + i*DD2,
            nullptr, xcoh_p, xcol_p, MTOK, DD2, DD2, DD2);

        // fc2|fc3 fused: xco(304) -> BC(256) f32
        mma_gemm<0><<<dim3(1, MBLK), 256, SMEM_TOTAL>>>(xcoh_p, xcol_p,
            w23h_p + (long)i*256*DD2, w23l_p + (long)i*256*DD2, b23_p + i*256,
            BC_p, nullptr, nullptr, MTOK, DD2, 256, 256);

        sdot_kernel<<<(MTOK*32 + 255)/256, 256>>>();

        // z = silu(xn @ D_w + D_b)
        mma_gemm<1><<<dim3(2, MBLK), 256, SMEM_TOTAL>>>(xnh_p, xnl_p,
            wdwh_p + (long)i*DD2*DM, wdwl_p + (long)i*DD2*DM, D_b + i*DD2,
            z_p, nullptr, nullptr, MTOK, DM, DD2, DD2);

        // fc1 + combine fused: -> cb split(304)
        mma_gemm<4><<<dim3(2, MBLK), 256, SMEM_TOTAL>>>(xcoh_p, xcol_p,
            wf1h_p + (long)i*DD2*DD2, wf1l_p + (long)i*DD2*DD2, fc1_b + i*DD2,
            nullptr, cbh_p, cbl_p, MTOK, DD2, DD2, DD2);

        // outproj: cb(304) -> h(152) f32
        mma_gemm<0><<<dim3(1, MBLK), 256, SMEM_TOTAL>>>(cbh_p, cbl_p,
            woph_p + (long)i*DM*DD2, wopl_p + (long)i*DM*DD2, outproj_b + i*DM,
            h_p, nullptr, nullptr, MTOK, DD2, DM, DM);
    }

    out_kernel<<<ROWS, 384>>>(W_out, b_out, out);
}

// round 5
// speedup vs baseline: 1.4328x; 1.4328x over previous
#include <cuda_runtime.h>
#include <cuda_bf16.h>
#include <math.h>
#include <stdint.h>

#define B_    8
#define T_    12
#define NN_   883
#define DM    152
#define DD2   304
#define SSZ   128
#define NL    3
#define STEPS 288
#define ROWS  (B_*NN_)          /* 7064  */
#define MTOK  (ROWS*T_)         /* 84768 */
#define MTILES ((MTOK+127)/128) /* 663   */

// ---------------- scratch (device globals; no allocs allowed) ----------------
__device__ float g_h [MTOK*DM];
__device__ float g_xp[MTOK*DD2];
__device__ float g_BC[MTOK*256];
__device__ float g_z [MTOK*DD2];
__device__ float g_s [MTOK];

__device__ __nv_bfloat16 g_xn_h [MTOK*DM],  g_xn_l [MTOK*DM];
__device__ __nv_bfloat16 g_xca_h[MTOK*DD2], g_xca_l[MTOK*DD2];
__device__ __nv_bfloat16 g_xco_h[MTOK*DD2], g_xco_l[MTOK*DD2];
__device__ __nv_bfloat16 g_cb_h [MTOK*DD2], g_cb_l [MTOK*DD2];

// split + transposed weights: [N rows, K cols] bf16
__device__ __nv_bfloat16 g_wipdw_h[NL*2*DD2*DM], g_wipdw_l[NL*2*DD2*DM]; /* 608 x 152 */
__device__ __nv_bfloat16 g_wcl_h[NL*DD2*DD2], g_wcl_l[NL*DD2*DD2];
__device__ __nv_bfloat16 g_w23_h[NL*256*DD2], g_w23_l[NL*256*DD2];
__device__ __nv_bfloat16 g_wf1_h[NL*DD2*DD2], g_wf1_l[NL*DD2*DD2];
__device__ __nv_bfloat16 g_wop_h[NL*DM*DD2],  g_wop_l[NL*DM*DD2];
__device__ float g_b23[NL*256];
__device__ float g_bipdw[NL*2*DD2];

__device__ __forceinline__ float siluf(float v)     { return v / (1.f + expf(-v)); }
__device__ __forceinline__ float softplusf(float v) { return (v > 20.f) ? v : log1pf(expf(v)); }

__device__ __forceinline__ uint32_t sm2u32(const void* p) {
    uint32_t a;
    asm("{ .reg .u64 t; cvta.to.shared.u64 t, %1; cvt.u32.u64 %0, t; }" : "=r"(a) : "l"(p));
    return a;
}
#define SWZ(o) ((uint32_t)(o) ^ ((((uint32_t)(o)) >> 3) & 0x70u))

__device__ __forceinline__ void ldsm4(uint32_t* r, uint32_t addr) {
    asm volatile("ldmatrix.sync.aligned.m8n8.x4.shared.b16 {%0,%1,%2,%3}, [%4];"
                 : "=r"(r[0]), "=r"(r[1]), "=r"(r[2]), "=r"(r[3]) : "r"(addr));
}
__device__ __forceinline__ void mma16816(float* c, const uint32_t* a, const uint32_t* b) {
    asm volatile("mma.sync.aligned.m16n8k16.row.col.f32.bf16.bf16.f32 "
                 "{%0,%1,%2,%3}, {%4,%5,%6,%7}, {%8,%9}, {%0,%1,%2,%3};"
                 : "+f"(c[0]), "+f"(c[1]), "+f"(c[2]), "+f"(c[3])
                 : "r"(a[0]), "r"(a[1]), "r"(a[2]), "r"(a[3]), "r"(b[0]), "r"(b[1]));
}

// ---------------- fused epilogue -------------------------------------------
// EPI: 0 bias->f32 | 3 bias->split bf16 | 4 fc1+combine->split bf16
//      5 dual: col<DD2 -> xp f32 ; col>=DD2 -> silu -> z f32
template<int EPI>
__device__ __forceinline__ void epi2(int m, int col, int ldc, float v0, float v1,
    const float* __restrict__ bias, float* Cf, float* Cf2,
    __nv_bfloat16* Ch, __nv_bfloat16* Cl)
{
    v0 += bias[col]; v1 += bias[col + 1];
    if (EPI == 4) {
        float sv = g_s[m];
        size_t off = (size_t)m * DD2 + col;
        float xc0 = __bfloat162float(g_xco_h[off])   + __bfloat162float(g_xco_l[off]);
        float xc1 = __bfloat162float(g_xco_h[off+1]) + __bfloat162float(g_xco_l[off+1]);
        v0 = siluf(xc0 * softplusf(v0) * sv) * g_z[off];
        v1 = siluf(xc1 * softplusf(v1) * sv) * g_z[off + 1];
    }
    if (EPI == 0) {
        *(float2*)(Cf + (size_t)m * ldc + col) = make_float2(v0, v1);
    } else if (EPI == 5) {
        if (col < DD2) {
            *(float2*)(Cf + (size_t)m * DD2 + col) = make_float2(v0, v1);
        } else {
            *(float2*)(Cf2 + (size_t)m * DD2 + (col - DD2)) =
                make_float2(siluf(v0), siluf(v1));
        }
    } else {
        __nv_bfloat16 h0 = __float2bfloat16(v0), h1 = __float2bfloat16(v1);
        __nv_bfloat16 l0 = __float2bfloat16(v0 - __bfloat162float(h0));
        __nv_bfloat16 l1 = __float2bfloat16(v1 - __bfloat162float(h1));
        *(__nv_bfloat162*)(Ch + (size_t)m * ldc + col) = __halves2bfloat162(h0, h1);
        *(__nv_bfloat162*)(Cl + (size_t)m * ldc + col) = __halves2bfloat162(l0, l1);
    }
}

// ---------------- GEMM: C[M,Nw] = epi(A[M,K] @ B[Nw,K]^T + bias) -------------
// CTA tile 128(M) x 128(N), K-chunk 64, serial smem fill (R3-proven mapping).
// 8 warps: wm = wid&3 (4 along M, 32 rows), wn = wid>>2 (2 along N, 64 cols).
#define SA_H 0
#define SA_L 16384
#define SB_H 32768
#define SB_L 49152
#define SM_TOTAL 65536

template<int EPI>
__global__ void __launch_bounds__(256, 2)
mma_gemm(const __nv_bfloat16* __restrict__ Ah, const __nv_bfloat16* __restrict__ Al,
         const __nv_bfloat16* __restrict__ Bh, const __nv_bfloat16* __restrict__ Bl,
         const float* __restrict__ bias,
         float* Cf, float* Cf2, __nv_bfloat16* Ch, __nv_bfloat16* Cl,
         int M, int K, int Nw, int ldc)
{
    extern __shared__ char smem[];
    const uint32_t sb = sm2u32(smem);
    const int tid  = threadIdx.x;
    const int lane = tid & 31;
    const int wid  = tid >> 5;
    const int wm   = wid & 3;      // 0..3 (M)
    const int wn   = wid >> 2;     // 0..1 (N)
    const int m0   = blockIdx.y * 128;
    const int n0   = blockIdx.x * 128;

    float acc[2][8][4];
#pragma unroll
    for (int i = 0; i < 2; i++)
#pragma unroll
        for (int j = 0; j < 8; j++)
#pragma unroll
            for (int q = 0; q < 4; q++) acc[i][j][q] = 0.f;

    for (int k0 = 0; k0 < K; k0 += 64) {
        // ---- fill A tile: 128 x 64 (hi & lo) ----
#pragma unroll
        for (int i = 0; i < 4; i++) {
            int idx = tid + i * 256;
            int r = idx >> 3, u = idx & 7;
            int gm = m0 + r, gk = k0 + u * 8;
            uint4 vh = make_uint4(0u,0u,0u,0u), vl = make_uint4(0u,0u,0u,0u);
            if (gm < M && gk < K) {
                vh = *(const uint4*)(Ah + (size_t)gm * K + gk);
                vl = *(const uint4*)(Al + (size_t)gm * K + gk);
            }
            uint32_t o = SWZ(r * 128 + u * 16);
            *(uint4*)(smem + SA_H + o) = vh;
            *(uint4*)(smem + SA_L + o) = vl;
        }
        // ---- fill B tile: 128 x 64 (hi & lo) ----
#pragma unroll
        for (int i = 0; i < 4; i++) {
            int idx = tid + i * 256;
            int r = idx >> 3, u = idx & 7;
            int gn = n0 + r, gk = k0 + u * 8;
            uint4 vh = make_uint4(0u,0u,0u,0u), vl = make_uint4(0u,0u,0u,0u);
            if (gn < Nw && gk < K) {
                vh = *(const uint4*)(Bh + (size_t)gn * K + gk);
                vl = *(const uint4*)(Bl + (size_t)gn * K + gk);
            }
            uint32_t o = SWZ(r * 128 + u * 16);
            *(uint4*)(smem + SB_H + o) = vh;
            *(uint4*)(smem + SB_L + o) = vl;
        }
        __syncthreads();

#pragma unroll
        for (int ks = 0; ks < 4; ks++) {
            const int kb = ks * 16;
            uint32_t ah[2][4], al[2][4];
#pragma unroll
            for (int mt = 0; mt < 2; mt++) {
                int row = wm * 32 + mt * 16 + (lane & 15);
                uint32_t o = SWZ(row * 128 + (kb + (lane >> 4) * 8) * 2);
                ldsm4(ah[mt], sb + SA_H + o);
                ldsm4(al[mt], sb + SA_L + o);
            }
            const int q = lane >> 3;
            const int rowo = (q >> 1) * 8 + (lane & 7);
            const int ko   = (q & 1) * 8;
#pragma unroll
            for (int p = 0; p < 4; p++) {
                int row = wn * 64 + p * 16 + rowo;
                uint32_t o = SWZ(row * 128 + (kb + ko) * 2);
                uint32_t rh[4], rl[4];
                ldsm4(rh, sb + SB_H + o);
                ldsm4(rl, sb + SB_L + o);
                uint32_t bh0[2] = {rh[0], rh[1]}, bh1[2] = {rh[2], rh[3]};
                uint32_t bl0[2] = {rl[0], rl[1]}, bl1[2] = {rl[2], rl[3]};
#pragma unroll
                for (int mt = 0; mt < 2; mt++) {
                    mma16816(acc[mt][2*p],   ah[mt], bh0);
                    mma16816(acc[mt][2*p],   ah[mt], bl0);
                    mma16816(acc[mt][2*p],   al[mt], bh0);
                    mma16816(acc[mt][2*p+1], ah[mt], bh1);
                    mma16816(acc[mt][2*p+1], ah[mt], bl1);
                    mma16816(acc[mt][2*p+1], al[mt], bh1);
                }
            }
        }
        __syncthreads();
    }

    // ---- epilogue ----
#pragma unroll
    for (int mt = 0; mt < 2; mt++) {
        int r0 = m0 + wm * 32 + mt * 16 + (lane >> 2);
        int r1 = r0 + 8;
#pragma unroll
        for (int nt = 0; nt < 8; nt++) {
            int col = n0 + wn * 64 + nt * 8 + (lane & 3) * 2;
            if (col < Nw) {
                if (r0 < M) epi2<EPI>(r0, col, ldc, acc[mt][nt][0], acc[mt][nt][1], bias, Cf, Cf2, Ch, Cl);
                if (r1 < M) epi2<EPI>(r1, col, ldc, acc[mt][nt][2], acc[mt][nt][3], bias, Cf, Cf2, Ch, Cl);
            }
        }
    }
}

// ---------------- weight transpose + split: W[K,N] -> Bt[N,K] hi/lo ----------
__global__ void wsplit(const float* __restrict__ W, __nv_bfloat16* __restrict__ oh,
                       __nv_bfloat16* __restrict__ ol, int K, int N)
{
    int idx = blockIdx.x * blockDim.x + threadIdx.x;
    if (idx >= K * N) return;
    int n = idx / K, k = idx % K;
    float v = W[(size_t)k * N + n];
    __nv_bfloat16 h = __float2bfloat16(v);
    oh[idx] = h;
    ol[idx] = __float2bfloat16(v - __bfloat162float(h));
}

__global__ void pack2(const float* __restrict__ a, const float* __restrict__ b,
                      float* __restrict__ dst, int na, int nb)
{
    int i = blockIdx.x * blockDim.x + threadIdx.x;
    if (i < na) dst[i] = a[i];
    else if (i < na + nb) dst[i] = b[i - na];
}

// ---------------- embedding ----------------
__global__ void embed_kernel(const float* __restrict__ x, const float* __restrict__ W_in,
                             const float* __restrict__ b_in, const float* __restrict__ tod,
                             const float* __restrict__ dow, const float* __restrict__ adp)
{
    long idx = blockIdx.x * (long)blockDim.x + threadIdx.x;
    if (idx >= (long)MTOK * DM) return;
    int  c      = (int)(idx % DM);
    long tokidx = idx / DM;
    int  t      = (int)(tokidx % T_);
    long rn     = tokidx / T_;
    int  n      = (int)(rn % NN_);
    int  b      = (int)(rn / NN_);
    const float* xe = x + (((long)(b * T_ + t) * NN_ + n) * 3);
    float v;
    if (c < 24) {
        v = b_in[c] + xe[0]*W_in[c] + xe[1]*W_in[24+c] + xe[2]*W_in[48+c];
    } else if (c < 48) {
        int ti = (int)(xe[1] * (float)STEPS);
        ti = min(max(ti, 0), STEPS - 1);
        v = tod[ti*24 + (c-24)];
    } else if (c < 72) {
        int di = (int)xe[2];
        di = min(max(di, 0), 6);
        v = dow[di*24 + (c-48)];
    } else {
        v = adp[((long)t * NN_ + n) * 80 + (c - 72)];
    }
    g_h[idx] = v;
}

// ---------------- rmsnorm -> split bf16 ----------------
__global__ void rmsnorm_kernel(const float* __restrict__ w)
{
    int gwarp = (blockIdx.x * blockDim.x + threadIdx.x) >> 5;
    int lane  = threadIdx.x & 31;
    if (gwarp >= MTOK) return;
    const float* row = g_h + (long)gwarp * DM;
    float ss = 0.f;
    for (int c = lane; c < DM; c += 32) { float v = row[c]; ss += v * v; }
#pragma unroll
    for (int o = 16; o; o >>= 1) ss += __shfl_xor_sync(0xffffffffu, ss, o);
    float scale = rsqrtf(ss / (float)DM + 1e-5f);
    long base = (long)gwarp * DM;
    for (int c = lane; c < DM; c += 32) {
        float v = row[c] * scale * w[c];
        __nv_bfloat16 h = __float2bfloat16(v);
        g_xn_h[base + c] = h;
        g_xn_l[base + c] = __float2bfloat16(v - __bfloat162float(h));
    }
}

// ---------------- conv over T + silu -> split bf16 (warp-aligned shfl) -------
// One warp handles 32 consecutive d within ONE row: 10 chunks of 32 cover 304.
#define DCHUNKS 10
__global__ void conv_silu_kernel(const float* __restrict__ cw, const float* __restrict__ cb)
{
    __shared__ float w[T_*T_*3];
    __shared__ float bsh[T_];
    for (int i = threadIdx.x; i < T_*T_*3; i += blockDim.x) w[i] = cw[i];
    for (int i = threadIdx.x; i < T_;      i += blockDim.x) bsh[i] = cb[i];
    __syncthreads();

    int gw = (int)((blockIdx.x * (long)blockDim.x + threadIdx.x) >> 5);
    if (gw >= ROWS * DCHUNKS) return;          // warp-uniform exit
    int lane = threadIdx.x & 31;
    int r  = gw / DCHUNKS;
    int dc = gw % DCHUNKS;
    int d  = dc * 32 + lane;
    int dl = min(d, DD2 - 1);
    const float* xrow = g_xp + (long)r * (T_ * DD2);

    float v1[T_];
#pragma unroll
    for (int ti = 0; ti < T_; ti++) v1[ti] = xrow[ti*DD2 + dl];

    float acc[T_];
#pragma unroll
    for (int to = 0; to < T_; to++) acc[to] = bsh[to];

#pragma unroll
    for (int ti = 0; ti < T_; ti++) {
        float v0 = __shfl_up_sync(0xffffffffu, v1[ti], 1);
        float v2 = __shfl_down_sync(0xffffffffu, v1[ti], 1);
        if (lane == 0)  v0 = (d > 0) ? xrow[ti*DD2 + d - 1] : 0.f;
        if (lane == 31) v2 = (d < DD2 - 1) ? xrow[ti*DD2 + d + 1] : 0.f;
        if (d >= DD2 - 1) v2 = 0.f;   // true right edge (incl. mid-warp in last chunk)
#pragma unroll
        for (int to = 0; to < T_; to++) {
            const float* wp = &w[(to*T_ + ti)*3];
            acc[to] += v0*wp[0] + v1[ti]*wp[1] + v2*wp[2];
        }
    }
    if (d < DD2) {
        long obase = (long)r * (T_ * DD2) + d;
#pragma unroll
        for (int to = 0; to < T_; to++) {
            float v = siluf(acc[to]);
            __nv_bfloat16 h = __float2bfloat16(v);
            g_xca_h[obase + to*DD2] = h;
            g_xca_l[obase + to*DD2] = __float2bfloat16(v - __bfloat162float(h));
        }
    }
}

// ---------------- s[token] = dot(BC[:,0:128], BC[:,128:256]) ----------------
__global__ void sdot_kernel()
{
    int gwarp = (blockIdx.x * blockDim.x + threadIdx.x) >> 5;
    int lane  = threadIdx.x & 31;
    if (gwarp >= MTOK) return;
    const float* row = g_BC + (long)gwarp * 256;
    float4 a = *(const float4*)(row + lane * 4);
    float4 b = *(const float4*)(row + 128 + lane * 4);
    float acc = a.x*b.x + a.y*b.y + a.z*b.z + a.w*b.w;
#pragma unroll
    for (int o = 16; o; o >>= 1) acc += __shfl_xor_sync(0xffffffffu, acc, o);
    if (!lane) g_s[gwarp] = acc;
}

// ---------------- head ----------------
__global__ void out_kernel(const float* __restrict__ Wout, const float* __restrict__ bout,
                           float* __restrict__ out)
{
    int rn   = blockIdx.x;
    int wj   = threadIdx.x >> 5;
    int lane = threadIdx.x & 31;
    const float* row = g_h + (long)rn * (T_ * DM);
    float acc = 0.f;
    for (int k = lane; k < T_ * DM; k += 32) acc += row[k] * Wout[k*12 + wj];
#pragma unroll
    for (int o = 16; o; o >>= 1) acc += __shfl_xor_sync(0xffffffffu, acc, o);
    if (!lane) {
        int n = rn % NN_, b = rn / NN_;
        out[((long)b * 12 + wj) * NN_ + n] = acc + bout[wj];
    }
}

// =============================================================================
extern "C" void kernel_launch(void* const* d_in, const int* in_sizes, int n_in,
                              void* d_out, int out_size)
{
    (void)in_sizes; (void)n_in; (void)out_size;
    const float* x        = (const float*)d_in[0];
    const float* W_in     = (const float*)d_in[1];
    const float* b_in     = (const float*)d_in[2];
    const float* tod      = (const float*)d_in[3];
    const float* dow      = (const float*)d_in[4];
    const float* adp      = (const float*)d_in[5];
    const float* norm_w   = (const float*)d_in[6];
    const float* inproj_w = (const float*)d_in[7];
    const float* inproj_b = (const float*)d_in[8];
    const float* conv_w   = (const float*)d_in[9];
    const float* conv_b   = (const float*)d_in[10];
    const float* convlin_w= (const float*)d_in[11];
    const float* convlin_b= (const float*)d_in[12];
    const float* fc1_w    = (const float*)d_in[13];
    const float* fc1_b    = (const float*)d_in[14];
    const float* fc2_w    = (const float*)d_in[15];
    const float* fc2_b    = (const float*)d_in[16];
    const float* fc3_w    = (const float*)d_in[17];
    const float* fc3_b    = (const float*)d_in[18];
    /* d_in[19] = A_ssm unused (h0 == 0) */
    const float* D_w      = (const float*)d_in[20];
    const float* D_b      = (const float*)d_in[21];
    const float* outproj_w= (const float*)d_in[22];
    const float* outproj_b= (const float*)d_in[23];
    const float* W_out    = (const float*)d_in[24];
    const float* b_out    = (const float*)d_in[25];
    float* out = (float*)d_out;

    cudaFuncSetAttribute(mma_gemm<0>, cudaFuncAttributeMaxDynamicSharedMemorySize, SM_TOTAL);
    cudaFuncSetAttribute(mma_gemm<3>, cudaFuncAttributeMaxDynamicSharedMemorySize, SM_TOTAL);
    cudaFuncSetAttribute(mma_gemm<4>, cudaFuncAttributeMaxDynamicSharedMemorySize, SM_TOTAL);
    cudaFuncSetAttribute(mma_gemm<5>, cudaFuncAttributeMaxDynamicSharedMemorySize, SM_TOTAL);

    void* p;
#define SYM(sym, var, ty) cudaGetSymbolAddress(&p, sym); ty* var = (ty*)p;
    SYM(g_xp,    xp_p,   float)
    SYM(g_BC,    BC_p,   float)
    SYM(g_z,     z_p,    float)
    SYM(g_b23,   b23_p,  float)
    SYM(g_bipdw, bipdw_p,float)
    SYM(g_h,     h_p,    float)
    SYM(g_xn_h,  xnh_p,  __nv_bfloat16)  SYM(g_xn_l,  xnl_p,  __nv_bfloat16)
    SYM(g_xca_h, xcah_p, __nv_bfloat16)  SYM(g_xca_l, xcal_p, __nv_bfloat16)
    SYM(g_xco_h, xcoh_p, __nv_bfloat16)  SYM(g_xco_l, xcol_p, __nv_bfloat16)
    SYM(g_cb_h,  cbh_p,  __nv_bfloat16)  SYM(g_cb_l,  cbl_p,  __nv_bfloat16)
    SYM(g_wipdw_h, wpdh_p, __nv_bfloat16) SYM(g_wipdw_l, wpdl_p, __nv_bfloat16)
    SYM(g_wcl_h, wclh_p, __nv_bfloat16)  SYM(g_wcl_l, wcll_p, __nv_bfloat16)
    SYM(g_w23_h, w23h_p, __nv_bfloat16)  SYM(g_w23_l, w23l_p, __nv_bfloat16)
    SYM(g_wf1_h, wf1h_p, __nv_bfloat16)  SYM(g_wf1_l, wf1l_p, __nv_bfloat16)
    SYM(g_wop_h, woph_p, __nv_bfloat16)  SYM(g_wop_l, wopl_p, __nv_bfloat16)
#undef SYM

    // ---- weight prep ----
    for (int i = 0; i < NL; i++) {
        long od = (long)i * 2 * DD2 * DM;
        wsplit<<<(DD2*DM + 255)/256, 256>>>(inproj_w + (long)i*DM*DD2,
            wpdh_p + od, wpdl_p + od, DM, DD2);
        wsplit<<<(DD2*DM + 255)/256, 256>>>(D_w + (long)i*DM*DD2,
            wpdh_p + od + (long)DD2*DM, wpdl_p + od + (long)DD2*DM, DM, DD2);
        pack2<<<3, 256>>>(inproj_b + i*DD2, D_b + i*DD2, bipdw_p + (long)i*2*DD2, DD2, DD2);

        wsplit<<<(DD2*DD2 + 255)/256, 256>>>(convlin_w + (long)i*DD2*DD2,
            wclh_p + (long)i*DD2*DD2, wcll_p + (long)i*DD2*DD2, DD2, DD2);
        wsplit<<<(SSZ*DD2 + 255)/256, 256>>>(fc2_w + (long)i*DD2*SSZ,
            w23h_p + (long)i*256*DD2,            w23l_p + (long)i*256*DD2, DD2, SSZ);
        wsplit<<<(SSZ*DD2 + 255)/256, 256>>>(fc3_w + (long)i*DD2*SSZ,
            w23h_p + (long)i*256*DD2 + 128*DD2,  w23l_p + (long)i*256*DD2 + 128*DD2, DD2, SSZ);
        pack2<<<1, 256>>>(fc2_b + i*SSZ, fc3_b + i*SSZ, b23_p + i*256, SSZ, SSZ);
        wsplit<<<(DD2*DD2 + 255)/256, 256>>>(fc1_w + (long)i*DD2*DD2,
            wf1h_p + (long)i*DD2*DD2, wf1l_p + (long)i*DD2*DD2, DD2, DD2);
        wsplit<<<(DM*DD2 + 255)/256, 256>>>(outproj_w + (long)i*DD2*DM,
            woph_p + (long)i*DM*DD2, wopl_p + (long)i*DM*DD2, DD2, DM);
    }

    // ---- embedding ----
    {
        long tot = (long)MTOK * DM;
        embed_kernel<<<(int)((tot + 255)/256), 256>>>(x, W_in, b_in, tod, dow, adp);
    }

    for (int i = 0; i < NL; i++) {
        rmsnorm_kernel<<<(MTOK*32 + 255)/256, 256>>>(norm_w + i*DM);

        // fused inproj | D_w : xn(152) -> xp(304 f32) & z(304 f32 silu), N=608
        mma_gemm<5><<<dim3(5, MTILES), 256, SM_TOTAL>>>(xnh_p, xnl_p,
            wpdh_p + (long)i*2*DD2*DM, wpdl_p + (long)i*2*DD2*DM, bipdw_p + (long)i*2*DD2,
            xp_p, z_p, nullptr, nullptr, MTOK, DM, 2*DD2, DD2);

        conv_silu_kernel<<<(ROWS*DCHUNKS*32 + 255)/256, 256>>>(conv_w + i*T_*T_*3, conv_b + i*T_);

        // convlin: xca(304) -> xco split(304)
        mma_gemm<3><<<dim3(3, MTILES), 256, SM_TOTAL>>>(xcah_p, xcal_p,
            wclh_p + (long)i*DD2*DD2, wcll_p + (long)i*DD2*DD2, convlin_b + i*DD2,
            nullptr, nullptr, xcoh_p, xcol_p, MTOK, DD2, DD2, DD2);

        // fc2|fc3 fused: xco(304) -> BC(256) f32
        mma_gemm<0><<<dim3(2, MTILES), 256, SM_TOTAL>>>(xcoh_p, xcol_p,
            w23h_p + (long)i*256*DD2, w23l_p + (long)i*256*DD2, b23_p + i*256,
            BC_p, nullptr, nullptr, nullptr, MTOK, DD2, 256, 256);

        sdot_kernel<<<(MTOK*32 + 255)/256, 256>>>();

        // fc1 + combine fused: -> cb split(304)
        mma_gemm<4><<<dim3(3, MTILES), 256, SM_TOTAL>>>(xcoh_p, xcol_p,
            wf1h_p + (long)i*DD2*DD2, wf1l_p + (long)i*DD2*DD2, fc1_b + i*DD2,
            nullptr, nullptr, cbh_p, cbl_p, MTOK, DD2, DD2, DD2);

        // outproj: cb(304) -> h(152) f32
        mma_gemm<0><<<dim3(2, MTILES), 256, SM_TOTAL>>>(cbh_p, cbl_p,
            woph_p + (long)i*DM*DD2, wopl_p + (long)i*DM*DD2, outproj_b + i*DM,
            h_p, nullptr, nullptr, nullptr, MTOK, DD2, DM, DM);
    }

    out_kernel<<<ROWS, 384>>>(W_out, b_out, out);
}

// round 6
// speedup vs baseline: 1.6449x; 1.1480x over previous
#include <cuda_runtime.h>
#include <cuda_bf16.h>
#include <math.h>
#include <stdint.h>

#define B_    8
#define T_    12
#define NN_   883
#define DM    152
#define DD2   304
#define SSZ   128
#define NL    3
#define STEPS 288
#define ROWS  (B_*NN_)          /* 7064  */
#define MTOK  (ROWS*T_)         /* 84768 */
#define MTILES ((MTOK+127)/128) /* 663   */

// ---------------- scratch (device globals; no allocs allowed) ----------------
__device__ float g_h [MTOK*DM];
__device__ float g_xp[MTOK*DD2];
__device__ float g_BC[MTOK*256];
__device__ float g_z [MTOK*DD2];
__device__ float g_s [MTOK];

__device__ __nv_bfloat16 g_xn_h [MTOK*DM],  g_xn_l [MTOK*DM];
__device__ __nv_bfloat16 g_xca_h[MTOK*DD2], g_xca_l[MTOK*DD2];
__device__ __nv_bfloat16 g_xco_h[MTOK*DD2], g_xco_l[MTOK*DD2];
__device__ __nv_bfloat16 g_cb_h [MTOK*DD2], g_cb_l [MTOK*DD2];

// split + transposed weights: [N rows, K cols] bf16
__device__ __nv_bfloat16 g_wipdw_h[NL*2*DD2*DM], g_wipdw_l[NL*2*DD2*DM]; /* 608x152 */
__device__ __nv_bfloat16 g_wcl_h[NL*DD2*DD2], g_wcl_l[NL*DD2*DD2];
__device__ __nv_bfloat16 g_w23_h[NL*256*DD2], g_w23_l[NL*256*DD2];
__device__ __nv_bfloat16 g_wf1_h[NL*DD2*DD2], g_wf1_l[NL*DD2*DD2];
__device__ __nv_bfloat16 g_wop_h[NL*DM*DD2],  g_wop_l[NL*DM*DD2];
__device__ float g_b23[NL*256];
__device__ float g_bipdw[NL*2*DD2];

__device__ __forceinline__ float siluf(float v)     { return v / (1.f + expf(-v)); }
__device__ __forceinline__ float softplusf(float v) { return (v > 20.f) ? v : log1pf(expf(v)); }

__device__ __forceinline__ uint32_t sm2u32(const void* p) {
    uint32_t a;
    asm("{ .reg .u64 t; cvta.to.shared.u64 t, %1; cvt.u32.u64 %0, t; }" : "=r"(a) : "l"(p));
    return a;
}
#define SWZ(o) ((uint32_t)(o) ^ ((((uint32_t)(o)) >> 3) & 0x70u))

__device__ __forceinline__ void ldsm4(uint32_t* r, uint32_t addr) {
    asm volatile("ldmatrix.sync.aligned.m8n8.x4.shared.b16 {%0,%1,%2,%3}, [%4];"
                 : "=r"(r[0]), "=r"(r[1]), "=r"(r[2]), "=r"(r[3]) : "r"(addr));
}
__device__ __forceinline__ void mma16816(float* c, const uint32_t* a, const uint32_t* b) {
    asm volatile("mma.sync.aligned.m16n8k16.row.col.f32.bf16.bf16.f32 "
                 "{%0,%1,%2,%3}, {%4,%5,%6,%7}, {%8,%9}, {%0,%1,%2,%3};"
                 : "+f"(c[0]), "+f"(c[1]), "+f"(c[2]), "+f"(c[3])
                 : "r"(a[0]), "r"(a[1]), "r"(a[2]), "r"(a[3]), "r"(b[0]), "r"(b[1]));
}
__device__ __forceinline__ void cpa16(uint32_t dst, const void* src, uint32_t sz) {
    asm volatile("cp.async.cg.shared.global [%0], [%1], 16, %2;"
                 :: "r"(dst), "l"(src), "r"(sz) : "memory");
}
__device__ __forceinline__ void cp_commit() {
    asm volatile("cp.async.commit_group;" ::: "memory");
}
template<int N>
__device__ __forceinline__ void cp_wait() {
    asm volatile("cp.async.wait_group %0;" :: "n"(N) : "memory");
}

// ---------------- fused epilogue -------------------------------------------
// EPI: 0 bias->f32 | 3 bias->split bf16 | 4 fc1+combine->split bf16
//      5 dual: col<DD2 -> xp f32 ; col>=DD2 -> silu -> z f32
template<int EPI>
__device__ __forceinline__ void epi2(int m, int col, int ldc, float v0, float v1,
    const float* __restrict__ bias, float* Cf, float* Cf2,
    __nv_bfloat16* Ch, __nv_bfloat16* Cl)
{
    v0 += bias[col]; v1 += bias[col + 1];
    if (EPI == 4) {
        float sv = g_s[m];
        size_t off = (size_t)m * DD2 + col;
        float xc0 = __bfloat162float(g_xco_h[off])   + __bfloat162float(g_xco_l[off]);
        float xc1 = __bfloat162float(g_xco_h[off+1]) + __bfloat162float(g_xco_l[off+1]);
        v0 = siluf(xc0 * softplusf(v0) * sv) * g_z[off];
        v1 = siluf(xc1 * softplusf(v1) * sv) * g_z[off + 1];
    }
    if (EPI == 0) {
        *(float2*)(Cf + (size_t)m * ldc + col) = make_float2(v0, v1);
    } else if (EPI == 5) {
        if (col < DD2) {
            *(float2*)(Cf + (size_t)m * DD2 + col) = make_float2(v0, v1);
        } else {
            *(float2*)(Cf2 + (size_t)m * DD2 + (col - DD2)) =
                make_float2(siluf(v0), siluf(v1));
        }
    } else {
        __nv_bfloat16 h0 = __float2bfloat16(v0), h1 = __float2bfloat16(v1);
        __nv_bfloat16 l0 = __float2bfloat16(v0 - __bfloat162float(h0));
        __nv_bfloat16 l1 = __float2bfloat16(v1 - __bfloat162float(h1));
        *(__nv_bfloat162*)(Ch + (size_t)m * ldc + col) = __halves2bfloat162(h0, h1);
        *(__nv_bfloat162*)(Cl + (size_t)m * ldc + col) = __halves2bfloat162(l0, l1);
    }
}

// ---------------- GEMM: C[M,Nw] = epi(A[M,K] @ B[Nw,K]^T + bias) -------------
// CTA tile 128(M) x 64(N), K-chunk 64, 2-stage cp.async, 2 CTAs/SM.
// 8 warps: wm = wid&3 (4 along M, 32 rows), wn = wid>>2 (2 along N, 32 cols).
#define STA_H 0
#define STA_L 16384
#define STB_H 32768
#define STB_L 40960
#define STG_SZ 49152
#define SM_TOTAL (2*STG_SZ)

template<int EPI>
__global__ void __launch_bounds__(256, 2)
mma_gemm(const __nv_bfloat16* __restrict__ Ah, const __nv_bfloat16* __restrict__ Al,
         const __nv_bfloat16* __restrict__ Bh, const __nv_bfloat16* __restrict__ Bl,
         const float* __restrict__ bias,
         float* Cf, float* Cf2, __nv_bfloat16* Ch, __nv_bfloat16* Cl,
         int M, int K, int Nw, int ldc)
{
    extern __shared__ char smem[];
    const uint32_t sb = sm2u32(smem);
    const int tid  = threadIdx.x;
    const int lane = tid & 31;
    const int wid  = tid >> 5;
    const int wm   = wid & 3;      // 0..3 (M)
    const int wn   = wid >> 2;     // 0..1 (N)
    const int m0   = blockIdx.y * 128;
    const int n0   = blockIdx.x * 64;

    float acc[2][4][4];
#pragma unroll
    for (int i = 0; i < 2; i++)
#pragma unroll
        for (int j = 0; j < 4; j++)
#pragma unroll
            for (int q = 0; q < 4; q++) acc[i][j][q] = 0.f;

    const int KC = (K + 63) >> 6;

    auto load_stage = [&](int stg, int k0) {
        uint32_t base = sb + stg * STG_SZ;
        // A: 128 rows x 64 k (hi & lo)
#pragma unroll
        for (int i = 0; i < 4; i++) {
            int idx = tid + i * 256;
            int r = idx >> 3, u = idx & 7;
            int gm = m0 + r, gk = k0 + u * 8;
            bool ok = (gm < M) && (gk < K);
            size_t go = (size_t)(ok ? gm : 0) * K + (ok ? gk : 0);
            uint32_t sz = ok ? 16u : 0u;
            uint32_t o = SWZ(r * 128 + u * 16);
            cpa16(base + STA_H + o, Ah + go, sz);
            cpa16(base + STA_L + o, Al + go, sz);
        }
        // B: 64 rows x 64 k (hi & lo)
#pragma unroll
        for (int i = 0; i < 2; i++) {
            int idx = tid + i * 256;
            int r = idx >> 3, u = idx & 7;
            int gn = n0 + r, gk = k0 + u * 8;
            bool ok = (gn < Nw) && (gk < K);
            size_t go = (size_t)(ok ? gn : 0) * K + (ok ? gk : 0);
            uint32_t sz = ok ? 16u : 0u;
            uint32_t o = SWZ(r * 128 + u * 16);
            cpa16(base + STB_H + o, Bh + go, sz);
            cpa16(base + STB_L + o, Bl + go, sz);
        }
    };

    load_stage(0, 0);
    cp_commit();

    for (int c = 0; c < KC; c++) {
        if (c + 1 < KC) {
            load_stage((c + 1) & 1, (c + 1) << 6);
            cp_commit();
            cp_wait<1>();
        } else {
            cp_wait<0>();
        }
        __syncthreads();

        const uint32_t base = sb + (c & 1) * STG_SZ;
#pragma unroll
        for (int ks = 0; ks < 4; ks++) {
            const int kb = ks * 16;
            uint32_t ah[2][4], al[2][4];
#pragma unroll
            for (int mt = 0; mt < 2; mt++) {
                int row = wm * 32 + mt * 16 + (lane & 15);
                uint32_t o = SWZ(row * 128 + (kb + (lane >> 4) * 8) * 2);
                ldsm4(ah[mt], base + STA_H + o);
                ldsm4(al[mt], base + STA_L + o);
            }
            const int q = lane >> 3;
            const int rowo = (q >> 1) * 8 + (lane & 7);
            const int ko   = (q & 1) * 8;
#pragma unroll
            for (int p = 0; p < 2; p++) {
                int row = wn * 32 + p * 16 + rowo;
                uint32_t o = SWZ(row * 128 + (kb + ko) * 2);
                uint32_t rh[4], rl[4];
                ldsm4(rh, base + STB_H + o);
                ldsm4(rl, base + STB_L + o);
                uint32_t bh0[2] = {rh[0], rh[1]}, bh1[2] = {rh[2], rh[3]};
                uint32_t bl0[2] = {rl[0], rl[1]}, bl1[2] = {rl[2], rl[3]};
#pragma unroll
                for (int mt = 0; mt < 2; mt++) {
                    mma16816(acc[mt][2*p],   ah[mt], bh0);
                    mma16816(acc[mt][2*p],   ah[mt], bl0);
                    mma16816(acc[mt][2*p],   al[mt], bh0);
                    mma16816(acc[mt][2*p+1], ah[mt], bh1);
                    mma16816(acc[mt][2*p+1], ah[mt], bl1);
                    mma16816(acc[mt][2*p+1], al[mt], bh1);
                }
            }
        }
        __syncthreads();
    }

    // ---- epilogue ----
#pragma unroll
    for (int mt = 0; mt < 2; mt++) {
        int r0 = m0 + wm * 32 + mt * 16 + (lane >> 2);
        int r1 = r0 + 8;
#pragma unroll
        for (int nt = 0; nt < 4; nt++) {
            int col = n0 + wn * 32 + nt * 8 + (lane & 3) * 2;
            if (col < Nw) {
                if (r0 < M) epi2<EPI>(r0, col, ldc, acc[mt][nt][0], acc[mt][nt][1], bias, Cf, Cf2, Ch, Cl);
                if (r1 < M) epi2<EPI>(r1, col, ldc, acc[mt][nt][2], acc[mt][nt][3], bias, Cf, Cf2, Ch, Cl);
            }
        }
    }
}

// ---------------- weight prep (3 launches total) ------------------------------
__device__ __forceinline__ void split_store(float v, __nv_bfloat16* oh, __nv_bfloat16* ol, long off) {
    __nv_bfloat16 h = __float2bfloat16(v);
    oh[off] = h;
    ol[off] = __float2bfloat16(v - __bfloat162float(h));
}

// ipdw: [608 x 152] per layer from inproj_w(152x304) | D_w(152x304)
__global__ void wprep_ipdw(const float* __restrict__ inw, const float* __restrict__ dww)
{
    int idx = blockIdx.x * blockDim.x + threadIdx.x;
    const int PER = 2 * DD2 * DM;
    if (idx >= NL * PER) return;
    int l = idx / PER, q = idx % PER;
    int n = q / DM, k = q % DM;
    float v = (n < DD2) ? inw[(size_t)l*DM*DD2 + k*DD2 + n]
                        : dww[(size_t)l*DM*DD2 + k*DD2 + (n - DD2)];
    split_store(v, g_wipdw_h, g_wipdw_l, idx);
}

// rest: convlin(304x304), w23(256x304), fc1(304x304), outproj(152x304)
#define SEG_CL  (DD2*DD2)           /* 92416 */
#define SEG_23  (256*DD2)           /* 77824 */
#define SEG_F1  (DD2*DD2)
#define SEG_OP  (DM*DD2)            /* 46208 */
#define SEG_ALL (SEG_CL+SEG_23+SEG_F1+SEG_OP)
__global__ void wprep_rest(const float* __restrict__ cl, const float* __restrict__ f2,
                           const float* __restrict__ f3, const float* __restrict__ f1,
                           const float* __restrict__ op)
{
    int idx = blockIdx.x * blockDim.x + threadIdx.x;
    if (idx >= NL * SEG_ALL) return;
    int l = idx / SEG_ALL, r = idx % SEG_ALL;
    if (r < SEG_CL) {
        int n = r / DD2, k = r % DD2;
        split_store(cl[(size_t)l*SEG_CL + (size_t)k*DD2 + n], g_wcl_h, g_wcl_l, (long)l*SEG_CL + r);
    } else if (r < SEG_CL + SEG_23) {
        int q = r - SEG_CL;
        int n = q / DD2, k = q % DD2;
        float v = (n < 128) ? f2[(size_t)l*DD2*SSZ + (size_t)k*SSZ + n]
                            : f3[(size_t)l*DD2*SSZ + (size_t)k*SSZ + (n - 128)];
        split_store(v, g_w23_h, g_w23_l, (long)l*SEG_23 + q);
    } else if (r < SEG_CL + SEG_23 + SEG_F1) {
        int q = r - SEG_CL - SEG_23;
        int n = q / DD2, k = q % DD2;
        split_store(f1[(size_t)l*SEG_F1 + (size_t)k*DD2 + n], g_wf1_h, g_wf1_l, (long)l*SEG_F1 + q);
    } else {
        int q = r - SEG_CL - SEG_23 - SEG_F1;
        int n = q / DD2, k = q % DD2;
        split_store(op[(size_t)l*SEG_OP + (size_t)k*DM + n], g_wop_h, g_wop_l, (long)l*SEG_OP + q);
    }
}

__global__ void pack_all(const float* __restrict__ inb, const float* __restrict__ db,
                         const float* __restrict__ f2b, const float* __restrict__ f3b)
{
    int i = blockIdx.x * blockDim.x + threadIdx.x;
    const int N1 = NL * 2 * DD2;
    if (i < N1) {
        int l = i / (2*DD2), j = i % (2*DD2);
        g_bipdw[i] = (j < DD2) ? inb[l*DD2 + j] : db[l*DD2 + (j - DD2)];
    } else if (i < N1 + NL*256) {
        int q = i - N1;
        int l = q / 256, j = q % 256;
        g_b23[q] = (j < 128) ? f2b[l*SSZ + j] : f3b[l*SSZ + (j - 128)];
    }
}

// ---------------- embedding ----------------
__global__ void embed_kernel(const float* __restrict__ x, const float* __restrict__ W_in,
                             const float* __restrict__ b_in, const float* __restrict__ tod,
                             const float* __restrict__ dow, const float* __restrict__ adp)
{
    long idx = blockIdx.x * (long)blockDim.x + threadIdx.x;
    if (idx >= (long)MTOK * DM) return;
    int  c      = (int)(idx % DM);
    long tokidx = idx / DM;
    int  t      = (int)(tokidx % T_);
    long rn     = tokidx / T_;
    int  n      = (int)(rn % NN_);
    int  b      = (int)(rn / NN_);
    const float* xe = x + (((long)(b * T_ + t) * NN_ + n) * 3);
    float v;
    if (c < 24) {
        v = b_in[c] + xe[0]*W_in[c] + xe[1]*W_in[24+c] + xe[2]*W_in[48+c];
    } else if (c < 48) {
        int ti = (int)(xe[1] * (float)STEPS);
        ti = min(max(ti, 0), STEPS - 1);
        v = tod[ti*24 + (c-24)];
    } else if (c < 72) {
        int di = (int)xe[2];
        di = min(max(di, 0), 6);
        v = dow[di*24 + (c-48)];
    } else {
        v = adp[((long)t * NN_ + n) * 80 + (c - 72)];
    }
    g_h[idx] = v;
}

// ---------------- rmsnorm -> split bf16 ----------------
__global__ void rmsnorm_kernel(const float* __restrict__ w)
{
    int gwarp = (blockIdx.x * blockDim.x + threadIdx.x) >> 5;
    int lane  = threadIdx.x & 31;
    if (gwarp >= MTOK) return;
    const float* row = g_h + (long)gwarp * DM;
    float ss = 0.f;
    for (int c = lane; c < DM; c += 32) { float v = row[c]; ss += v * v; }
#pragma unroll
    for (int o = 16; o; o >>= 1) ss += __shfl_xor_sync(0xffffffffu, ss, o);
    float scale = rsqrtf(ss / (float)DM + 1e-5f);
    long base = (long)gwarp * DM;
    for (int c = lane; c < DM; c += 32) {
        float v = row[c] * scale * w[c];
        __nv_bfloat16 h = __float2bfloat16(v);
        g_xn_h[base + c] = h;
        g_xn_l[base + c] = __float2bfloat16(v - __bfloat162float(h));
    }
}

// ---------------- conv over T + silu -> split bf16 (warp-aligned shfl) -------
#define DCHUNKS 10
__global__ void conv_silu_kernel(const float* __restrict__ cw, const float* __restrict__ cb)
{
    __shared__ float w[T_*T_*3];
    __shared__ float bsh[T_];
    for (int i = threadIdx.x; i < T_*T_*3; i += blockDim.x) w[i] = cw[i];
    for (int i = threadIdx.x; i < T_;      i += blockDim.x) bsh[i] = cb[i];
    __syncthreads();

    int gw = (int)((blockIdx.x * (long)blockDim.x + threadIdx.x) >> 5);
    if (gw >= ROWS * DCHUNKS) return;
    int lane = threadIdx.x & 31;
    int r  = gw / DCHUNKS;
    int dc = gw % DCHUNKS;
    int d  = dc * 32 + lane;
    int dl = min(d, DD2 - 1);
    const float* xrow = g_xp + (long)r * (T_ * DD2);

    float v1[T_];
#pragma unroll
    for (int ti = 0; ti < T_; ti++) v1[ti] = xrow[ti*DD2 + dl];

    float acc[T_];
#pragma unroll
    for (int to = 0; to < T_; to++) acc[to] = bsh[to];

#pragma unroll
    for (int ti = 0; ti < T_; ti++) {
        float v0 = __shfl_up_sync(0xffffffffu, v1[ti], 1);
        float v2 = __shfl_down_sync(0xffffffffu, v1[ti], 1);
        if (lane == 0)  v0 = (d > 0) ? xrow[ti*DD2 + d - 1] : 0.f;
        if (lane == 31) v2 = (d < DD2 - 1) ? xrow[ti*DD2 + d + 1] : 0.f;
        if (d >= DD2 - 1) v2 = 0.f;
#pragma unroll
        for (int to = 0; to < T_; to++) {
            const float* wp = &w[(to*T_ + ti)*3];
            acc[to] += v0*wp[0] + v1[ti]*wp[1] + v2*wp[2];
        }
    }
    if (d < DD2) {
        long obase = (long)r * (T_ * DD2) + d;
#pragma unroll
        for (int to = 0; to < T_; to++) {
            float v = siluf(acc[to]);
            __nv_bfloat16 h = __float2bfloat16(v);
            g_xca_h[obase + to*DD2] = h;
            g_xca_l[obase + to*DD2] = __float2bfloat16(v - __bfloat162float(h));
        }
    }
}

// ---------------- s[token] = dot(BC[:,0:128], BC[:,128:256]) ----------------
__global__ void sdot_kernel()
{
    int gwarp = (blockIdx.x * blockDim.x + threadIdx.x) >> 5;
    int lane  = threadIdx.x & 31;
    if (gwarp >= MTOK) return;
    const float* row = g_BC + (long)gwarp * 256;
    float4 a = *(const float4*)(row + lane * 4);
    float4 b = *(const float4*)(row + 128 + lane * 4);
    float acc = a.x*b.x + a.y*b.y + a.z*b.z + a.w*b.w;
#pragma unroll
    for (int o = 16; o; o >>= 1) acc += __shfl_xor_sync(0xffffffffu, acc, o);
    if (!lane) g_s[gwarp] = acc;
}

// ---------------- head ----------------
__global__ void out_kernel(const float* __restrict__ Wout, const float* __restrict__ bout,
                           float* __restrict__ out)
{
    int rn   = blockIdx.x;
    int wj   = threadIdx.x >> 5;
    int lane = threadIdx.x & 31;
    const float* row = g_h + (long)rn * (T_ * DM);
    float acc = 0.f;
    for (int k = lane; k < T_ * DM; k += 32) acc += row[k] * Wout[k*12 + wj];
#pragma unroll
    for (int o = 16; o; o >>= 1) acc += __shfl_xor_sync(0xffffffffu, acc, o);
    if (!lane) {
        int n = rn % NN_, b = rn / NN_;
        out[((long)b * 12 + wj) * NN_ + n] = acc + bout[wj];
    }
}

// =============================================================================
extern "C" void kernel_launch(void* const* d_in, const int* in_sizes, int n_in,
                              void* d_out, int out_size)
{
    (void)in_sizes; (void)n_in; (void)out_size;
    const float* x        = (const float*)d_in[0];
    const float* W_in     = (const float*)d_in[1];
    const float* b_in     = (const float*)d_in[2];
    const float* tod      = (const float*)d_in[3];
    const float* dow      = (const float*)d_in[4];
    const float* adp      = (const float*)d_in[5];
    const float* norm_w   = (const float*)d_in[6];
    const float* inproj_w = (const float*)d_in[7];
    const float* inproj_b = (const float*)d_in[8];
    const float* conv_w   = (const float*)d_in[9];
    const float* conv_b   = (const float*)d_in[10];
    const float* convlin_w= (const float*)d_in[11];
    const float* convlin_b= (const float*)d_in[12];
    const float* fc1_w    = (const float*)d_in[13];
    const float* fc1_b    = (const float*)d_in[14];
    const float* fc2_w    = (const float*)d_in[15];
    const float* fc2_b    = (const float*)d_in[16];
    const float* fc3_w    = (const float*)d_in[17];
    const float* fc3_b    = (const float*)d_in[18];
    /* d_in[19] = A_ssm unused (h0 == 0) */
    const float* D_w      = (const float*)d_in[20];
    const float* D_b      = (const float*)d_in[21];
    const float* outproj_w= (const float*)d_in[22];
    const float* outproj_b= (const float*)d_in[23];
    const float* W_out    = (const float*)d_in[24];
    const float* b_out    = (const float*)d_in[25];
    float* out = (float*)d_out;

    cudaFuncSetAttribute(mma_gemm<0>, cudaFuncAttributeMaxDynamicSharedMemorySize, SM_TOTAL);
    cudaFuncSetAttribute(mma_gemm<3>, cudaFuncAttributeMaxDynamicSharedMemorySize, SM_TOTAL);
    cudaFuncSetAttribute(mma_gemm<4>, cudaFuncAttributeMaxDynamicSharedMemorySize, SM_TOTAL);
    cudaFuncSetAttribute(mma_gemm<5>, cudaFuncAttributeMaxDynamicSharedMemorySize, SM_TOTAL);

    void* p;
#define SYM(sym, var, ty) cudaGetSymbolAddress(&p, sym); ty* var = (ty*)p;
    SYM(g_xp,    xp_p,   float)
    SYM(g_BC,    BC_p,   float)
    SYM(g_z,     z_p,    float)
    SYM(g_b23,   b23_p,  float)
    SYM(g_bipdw, bipdw_p,float)
    SYM(g_h,     h_p,    float)
    SYM(g_xn_h,  xnh_p,  __nv_bfloat16)  SYM(g_xn_l,  xnl_p,  __nv_bfloat16)
    SYM(g_xca_h, xcah_p, __nv_bfloat16)  SYM(g_xca_l, xcal_p, __nv_bfloat16)
    SYM(g_xco_h, xcoh_p, __nv_bfloat16)  SYM(g_xco_l, xcol_p, __nv_bfloat16)
    SYM(g_cb_h,  cbh_p,  __nv_bfloat16)  SYM(g_cb_l,  cbl_p,  __nv_bfloat16)
    SYM(g_wipdw_h, wpdh_p, __nv_bfloat16) SYM(g_wipdw_l, wpdl_p, __nv_bfloat16)
    SYM(g_wcl_h, wclh_p, __nv_bfloat16)  SYM(g_wcl_l, wcll_p, __nv_bfloat16)
    SYM(g_w23_h, w23h_p, __nv_bfloat16)  SYM(g_w23_l, w23l_p, __nv_bfloat16)
    SYM(g_wf1_h, wf1h_p, __nv_bfloat16)  SYM(g_wf1_l, wf1l_p, __nv_bfloat16)
    SYM(g_wop_h, woph_p, __nv_bfloat16)  SYM(g_wop_l, wopl_p, __nv_bfloat16)
#undef SYM

    // ---- launches 0-2: weight prep (keeps launch idx 5 == first GEMM for ncu)
    wprep_ipdw<<<(NL*2*DD2*DM + 255)/256, 256>>>(inproj_w, D_w);
    wprep_rest<<<(NL*SEG_ALL + 255)/256, 256>>>(convlin_w, fc2_w, fc3_w, fc1_w, outproj_w);
    pack_all<<<(NL*2*DD2 + NL*256 + 255)/256, 256>>>(inproj_b, D_b, fc2_b, fc3_b);

    // ---- launch 3: embedding
    {
        long tot = (long)MTOK * DM;
        embed_kernel<<<(int)((tot + 255)/256), 256>>>(x, W_in, b_in, tod, dow, adp);
    }

    for (int i = 0; i < NL; i++) {
        // launch 4 (+...): rmsnorm
        rmsnorm_kernel<<<(MTOK*32 + 255)/256, 256>>>(norm_w + i*DM);

        // launch 5 on layer 0: fused inproj|D_w : xn(152) -> xp & z, N=608
        mma_gemm<5><<<dim3(10, MTILES), 256, SM_TOTAL>>>(xnh_p, xnl_p,
            wpdh_p + (long)i*2*DD2*DM, wpdl_p + (long)i*2*DD2*DM, bipdw_p + (long)i*2*DD2,
            xp_p, z_p, nullptr, nullptr, MTOK, DM, 2*DD2, DD2);

        conv_silu_kernel<<<(ROWS*DCHUNKS*32 + 255)/256, 256>>>(conv_w + i*T_*T_*3, conv_b + i*T_);

        // convlin: xca(304) -> xco split(304)
        mma_gemm<3><<<dim3(5, MTILES), 256, SM_TOTAL>>>(xcah_p, xcal_p,
            wclh_p + (long)i*DD2*DD2, wcll_p + (long)i*DD2*DD2, convlin_b + i*DD2,
            nullptr, nullptr, xcoh_p, xcol_p, MTOK, DD2, DD2, DD2);

        // fc2|fc3 fused: xco(304) -> BC(256) f32
        mma_gemm<0><<<dim3(4, MTILES), 256, SM_TOTAL>>>(xcoh_p, xcol_p,
            w23h_p + (long)i*256*DD2, w23l_p + (long)i*256*DD2, b23_p + i*256,
            BC_p, nullptr, nullptr, nullptr, MTOK, DD2, 256, 256);

        sdot_kernel<<<(MTOK*32 + 255)/256, 256>>>();

        // fc1 + combine fused: -> cb split(304)
        mma_gemm<4><<<dim3(5, MTILES), 256, SM_TOTAL>>>(xcoh_p, xcol_p,
            wf1h_p + (long)i*DD2*DD2, wf1l_p + (long)i*DD2*DD2, fc1_b + i*DD2,
            nullptr, nullptr, cbh_p, cbl_p, MTOK, DD2, DD2, DD2);

        // outproj: cb(304) -> h(152) f32
        mma_gemm<0><<<dim3(3, MTILES), 256, SM_TOTAL>>>(cbh_p, cbl_p,
            woph_p + (long)i*DM*DD2, wopl_p + (long)i*DM*DD2, outproj_b + i*DM,
            h_p, nullptr, nullptr, nullptr, MTOK, DD2, DM, DM);
    }

    out_kernel<<<ROWS, 384>>>(W_out, b_out, out);
}

// round 7
// speedup vs baseline: 2.5451x; 1.5473x over previous
#include <cuda_runtime.h>
#include <cuda_fp16.h>
#include <math.h>
#include <stdint.h>

#define B_    8
#define T_    12
#define NN_   883
#define DM    152
#define DD2   304
#define SSZ   128
#define NL    3
#define STEPS 288
#define ROWS  (B_*NN_)          /* 7064  */
#define MTOK  (ROWS*T_)         /* 84768 */
#define MTILES ((MTOK+127)/128) /* 663   */

// ---------------- scratch (device globals; no allocs allowed) ----------------
__device__ float g_h [MTOK*DM];
__device__ float g_xp[MTOK*DD2];
__device__ float g_BC[MTOK*256];
__device__ float g_z [MTOK*DD2];
__device__ float g_s [MTOK];

__device__ __half g_xn [MTOK*DM];
__device__ __half g_xca[MTOK*DD2];
__device__ __half g_xco[MTOK*DD2];
__device__ __half g_cb [MTOK*DD2];

// transposed fp16 weights: [N rows, K cols]
__device__ __half g_wipdw[NL*2*DD2*DM];   /* 608 x 152 */
__device__ __half g_wcl  [NL*DD2*DD2];
__device__ __half g_w23  [NL*256*DD2];
__device__ __half g_wf1  [NL*DD2*DD2];
__device__ __half g_wop  [NL*DM*DD2];
__device__ float  g_b23  [NL*256];
__device__ float  g_bipdw[NL*2*DD2];

__device__ __forceinline__ float siluf(float v)     { return v / (1.f + expf(-v)); }
__device__ __forceinline__ float softplusf(float v) { return (v > 20.f) ? v : log1pf(expf(v)); }

__device__ __forceinline__ uint32_t sm2u32(const void* p) {
    uint32_t a;
    asm("{ .reg .u64 t; cvta.to.shared.u64 t, %1; cvt.u32.u64 %0, t; }" : "=r"(a) : "l"(p));
    return a;
}
#define SWZ(o) ((uint32_t)(o) ^ ((((uint32_t)(o)) >> 3) & 0x70u))

__device__ __forceinline__ void ldsm4(uint32_t* r, uint32_t addr) {
    asm volatile("ldmatrix.sync.aligned.m8n8.x4.shared.b16 {%0,%1,%2,%3}, [%4];"
                 : "=r"(r[0]), "=r"(r[1]), "=r"(r[2]), "=r"(r[3]) : "r"(addr));
}
__device__ __forceinline__ void mma16816(float* c, const uint32_t* a, const uint32_t* b) {
    asm volatile("mma.sync.aligned.m16n8k16.row.col.f32.f16.f16.f32 "
                 "{%0,%1,%2,%3}, {%4,%5,%6,%7}, {%8,%9}, {%0,%1,%2,%3};"
                 : "+f"(c[0]), "+f"(c[1]), "+f"(c[2]), "+f"(c[3])
                 : "r"(a[0]), "r"(a[1]), "r"(a[2]), "r"(a[3]), "r"(b[0]), "r"(b[1]));
}
__device__ __forceinline__ void cpa16(uint32_t dst, const void* src, uint32_t sz) {
    asm volatile("cp.async.cg.shared.global [%0], [%1], 16, %2;"
                 :: "r"(dst), "l"(src), "r"(sz) : "memory");
}
__device__ __forceinline__ void cp_commit() {
    asm volatile("cp.async.commit_group;" ::: "memory");
}
template<int N>
__device__ __forceinline__ void cp_wait() {
    asm volatile("cp.async.wait_group %0;" :: "n"(N) : "memory");
}

// ---------------- fused epilogue -------------------------------------------
// EPI: 0 bias->f32 | 3 bias->fp16 | 4 fc1+combine->fp16
//      5 dual: col<DD2 -> xp f32 ; col>=DD2 -> silu -> z f32
template<int EPI>
__device__ __forceinline__ void epi2(int m, int col, int ldc, float v0, float v1,
    const float* __restrict__ bias, float* Cf, float* Cf2, __half* Ch)
{
    v0 += bias[col]; v1 += bias[col + 1];
    if (EPI == 4) {
        float sv = g_s[m];
        size_t off = (size_t)m * DD2 + col;
        float xc0 = __half2float(g_xco[off]);
        float xc1 = __half2float(g_xco[off + 1]);
        v0 = siluf(xc0 * softplusf(v0) * sv) * g_z[off];
        v1 = siluf(xc1 * softplusf(v1) * sv) * g_z[off + 1];
    }
    if (EPI == 0) {
        *(float2*)(Cf + (size_t)m * ldc + col) = make_float2(v0, v1);
    } else if (EPI == 5) {
        if (col < DD2) {
            *(float2*)(Cf + (size_t)m * DD2 + col) = make_float2(v0, v1);
        } else {
            *(float2*)(Cf2 + (size_t)m * DD2 + (col - DD2)) =
                make_float2(siluf(v0), siluf(v1));
        }
    } else {
        *(__half2*)(Ch + (size_t)m * ldc + col) =
            __halves2half2(__float2half(v0), __float2half(v1));
    }
}

// ---------------- GEMM: C[M,Nw] = epi(A[M,K] @ B[Nw,K]^T + bias) -------------
// CTA tile 128(M) x 128(N), K-chunk 64, 2-stage cp.async, 2 CTAs/SM.
// 8 warps: wm = wid&3 (4 along M, 32 rows), wn = wid>>2 (2 along N, 64 cols).
#define STA 0
#define STB 16384
#define STG_SZ 32768
#define SM_TOTAL (2*STG_SZ)

template<int EPI>
__global__ void __launch_bounds__(256, 2)
mma_gemm(const __half* __restrict__ A, const __half* __restrict__ B,
         const float* __restrict__ bias,
         float* Cf, float* Cf2, __half* Ch,
         int M, int K, int Nw, int ldc)
{
    extern __shared__ char smem[];
    const uint32_t sb = sm2u32(smem);
    const int tid  = threadIdx.x;
    const int lane = tid & 31;
    const int wid  = tid >> 5;
    const int wm   = wid & 3;      // 0..3 (M)
    const int wn   = wid >> 2;     // 0..1 (N)
    const int m0   = blockIdx.y * 128;
    const int n0   = blockIdx.x * 128;

    float acc[2][8][4];
#pragma unroll
    for (int i = 0; i < 2; i++)
#pragma unroll
        for (int j = 0; j < 8; j++)
#pragma unroll
            for (int q = 0; q < 4; q++) acc[i][j][q] = 0.f;

    const int KC = (K + 63) >> 6;

    auto load_stage = [&](int stg, int k0) {
        uint32_t base = sb + stg * STG_SZ;
#pragma unroll
        for (int i = 0; i < 4; i++) {          // A: 128 rows x 64 k
            int idx = tid + i * 256;
            int r = idx >> 3, u = idx & 7;
            int gm = m0 + r, gk = k0 + u * 8;
            bool ok = (gm < M) && (gk < K);
            size_t go = (size_t)(ok ? gm : 0) * K + (ok ? gk : 0);
            cpa16(base + STA + SWZ(r * 128 + u * 16), A + go, ok ? 16u : 0u);
        }
#pragma unroll
        for (int i = 0; i < 4; i++) {          // B: 128 rows x 64 k
            int idx = tid + i * 256;
            int r = idx >> 3, u = idx & 7;
            int gn = n0 + r, gk = k0 + u * 8;
            bool ok = (gn < Nw) && (gk < K);
            size_t go = (size_t)(ok ? gn : 0) * K + (ok ? gk : 0);
            cpa16(base + STB + SWZ(r * 128 + u * 16), B + go, ok ? 16u : 0u);
        }
    };

    load_stage(0, 0);
    cp_commit();

    for (int c = 0; c < KC; c++) {
        if (c + 1 < KC) {
            load_stage((c + 1) & 1, (c + 1) << 6);
            cp_commit();
            cp_wait<1>();
        } else {
            cp_wait<0>();
        }
        __syncthreads();

        const uint32_t base = sb + (c & 1) * STG_SZ;
#pragma unroll
        for (int ks = 0; ks < 4; ks++) {
            const int kb = ks * 16;
            uint32_t ah[2][4];
#pragma unroll
            for (int mt = 0; mt < 2; mt++) {
                int row = wm * 32 + mt * 16 + (lane & 15);
                ldsm4(ah[mt], base + STA + SWZ(row * 128 + (kb + (lane >> 4) * 8) * 2));
            }
            const int q = lane >> 3;
            const int rowo = (q >> 1) * 8 + (lane & 7);
            const int ko   = (q & 1) * 8;
            uint32_t bf[8][2];
#pragma unroll
            for (int p = 0; p < 4; p++) {
                int row = wn * 64 + p * 16 + rowo;
                uint32_t r4[4];
                ldsm4(r4, base + STB + SWZ(row * 128 + (kb + ko) * 2));
                bf[2*p][0] = r4[0]; bf[2*p][1] = r4[1];
                bf[2*p+1][0] = r4[2]; bf[2*p+1][1] = r4[3];
            }
#pragma unroll
            for (int mt = 0; mt < 2; mt++)
#pragma unroll
                for (int nt = 0; nt < 8; nt++)
                    mma16816(acc[mt][nt], ah[mt], bf[nt]);
        }
        __syncthreads();
    }

    // ---- epilogue ----
#pragma unroll
    for (int mt = 0; mt < 2; mt++) {
        int r0 = m0 + wm * 32 + mt * 16 + (lane >> 2);
        int r1 = r0 + 8;
#pragma unroll
        for (int nt = 0; nt < 8; nt++) {
            int col = n0 + wn * 64 + nt * 8 + (lane & 3) * 2;
            if (col < Nw) {
                if (r0 < M) epi2<EPI>(r0, col, ldc, acc[mt][nt][0], acc[mt][nt][1], bias, Cf, Cf2, Ch);
                if (r1 < M) epi2<EPI>(r1, col, ldc, acc[mt][nt][2], acc[mt][nt][3], bias, Cf, Cf2, Ch);
            }
        }
    }
}

// ---------------- weight prep (3 launches total) ------------------------------
__global__ void wprep_ipdw(const float* __restrict__ inw, const float* __restrict__ dww)
{
    int idx = blockIdx.x * blockDim.x + threadIdx.x;
    const int PER = 2 * DD2 * DM;
    if (idx >= NL * PER) return;
    int l = idx / PER, q = idx % PER;
    int n = q / DM, k = q % DM;
    float v = (n < DD2) ? inw[(size_t)l*DM*DD2 + k*DD2 + n]
                        : dww[(size_t)l*DM*DD2 + k*DD2 + (n - DD2)];
    g_wipdw[idx] = __float2half(v);
}

#define SEG_CL  (DD2*DD2)
#define SEG_23  (256*DD2)
#define SEG_F1  (DD2*DD2)
#define SEG_OP  (DM*DD2)
#define SEG_ALL (SEG_CL+SEG_23+SEG_F1+SEG_OP)
__global__ void wprep_rest(const float* __restrict__ cl, const float* __restrict__ f2,
                           const float* __restrict__ f3, const float* __restrict__ f1,
                           const float* __restrict__ op)
{
    int idx = blockIdx.x * blockDim.x + threadIdx.x;
    if (idx >= NL * SEG_ALL) return;
    int l = idx / SEG_ALL, r = idx % SEG_ALL;
    if (r < SEG_CL) {
        int n = r / DD2, k = r % DD2;
        g_wcl[(long)l*SEG_CL + r] = __float2half(cl[(size_t)l*SEG_CL + (size_t)k*DD2 + n]);
    } else if (r < SEG_CL + SEG_23) {
        int q = r - SEG_CL;
        int n = q / DD2, k = q % DD2;
        float v = (n < 128) ? f2[(size_t)l*DD2*SSZ + (size_t)k*SSZ + n]
                            : f3[(size_t)l*DD2*SSZ + (size_t)k*SSZ + (n - 128)];
        g_w23[(long)l*SEG_23 + q] = __float2half(v);
    } else if (r < SEG_CL + SEG_23 + SEG_F1) {
        int q = r - SEG_CL - SEG_23;
        int n = q / DD2, k = q % DD2;
        g_wf1[(long)l*SEG_F1 + q] = __float2half(f1[(size_t)l*SEG_F1 + (size_t)k*DD2 + n]);
    } else {
        int q = r - SEG_CL - SEG_23 - SEG_F1;
        int n = q / DD2, k = q % DD2;
        g_wop[(long)l*SEG_OP + q] = __float2half(op[(size_t)l*SEG_OP + (size_t)k*DM + n]);
    }
}

__global__ void pack_all(const float* __restrict__ inb, const float* __restrict__ db,
                         const float* __restrict__ f2b, const float* __restrict__ f3b)
{
    int i = blockIdx.x * blockDim.x + threadIdx.x;
    const int N1 = NL * 2 * DD2;
    if (i < N1) {
        int l = i / (2*DD2), j = i % (2*DD2);
        g_bipdw[i] = (j < DD2) ? inb[l*DD2 + j] : db[l*DD2 + (j - DD2)];
    } else if (i < N1 + NL*256) {
        int q = i - N1;
        int l = q / 256, j = q % 256;
        g_b23[q] = (j < 128) ? f2b[l*SSZ + j] : f3b[l*SSZ + (j - 128)];
    }
}

// ---------------- embedding ----------------
__global__ void embed_kernel(const float* __restrict__ x, const float* __restrict__ W_in,
                             const float* __restrict__ b_in, const float* __restrict__ tod,
                             const float* __restrict__ dow, const float* __restrict__ adp)
{
    long idx = blockIdx.x * (long)blockDim.x + threadIdx.x;
    if (idx >= (long)MTOK * DM) return;
    int  c      = (int)(idx % DM);
    long tokidx = idx / DM;
    int  t      = (int)(tokidx % T_);
    long rn     = tokidx / T_;
    int  n      = (int)(rn % NN_);
    int  b      = (int)(rn / NN_);
    const float* xe = x + (((long)(b * T_ + t) * NN_ + n) * 3);
    float v;
    if (c < 24) {
        v = b_in[c] + xe[0]*W_in[c] + xe[1]*W_in[24+c] + xe[2]*W_in[48+c];
    } else if (c < 48) {
        int ti = (int)(xe[1] * (float)STEPS);
        ti = min(max(ti, 0), STEPS - 1);
        v = tod[ti*24 + (c-24)];
    } else if (c < 72) {
        int di = (int)xe[2];
        di = min(max(di, 0), 6);
        v = dow[di*24 + (c-48)];
    } else {
        v = adp[((long)t * NN_ + n) * 80 + (c - 72)];
    }
    g_h[idx] = v;
}

// ---------------- rmsnorm -> fp16 ----------------
__global__ void rmsnorm_kernel(const float* __restrict__ w)
{
    int gwarp = (blockIdx.x * blockDim.x + threadIdx.x) >> 5;
    int lane  = threadIdx.x & 31;
    if (gwarp >= MTOK) return;
    const float* row = g_h + (long)gwarp * DM;
    float ss = 0.f;
    for (int c = lane; c < DM; c += 32) { float v = row[c]; ss += v * v; }
#pragma unroll
    for (int o = 16; o; o >>= 1) ss += __shfl_xor_sync(0xffffffffu, ss, o);
    float scale = rsqrtf(ss / (float)DM + 1e-5f);
    long base = (long)gwarp * DM;
    for (int c = lane; c < DM; c += 32)
        g_xn[base + c] = __float2half(row[c] * scale * w[c]);
}

// ---------------- conv over T + silu -> fp16 (warp-aligned shfl) -------------
#define DCHUNKS 10
__global__ void conv_silu_kernel(const float* __restrict__ cw, const float* __restrict__ cb)
{
    __shared__ float w[T_*T_*3];
    __shared__ float bsh[T_];
    for (int i = threadIdx.x; i < T_*T_*3; i += blockDim.x) w[i] = cw[i];
    for (int i = threadIdx.x; i < T_;      i += blockDim.x) bsh[i] = cb[i];
    __syncthreads();

    int gw = (int)((blockIdx.x * (long)blockDim.x + threadIdx.x) >> 5);
    if (gw >= ROWS * DCHUNKS) return;
    int lane = threadIdx.x & 31;
    int r  = gw / DCHUNKS;
    int dc = gw % DCHUNKS;
    int d  = dc * 32 + lane;
    int dl = min(d, DD2 - 1);
    const float* xrow = g_xp + (long)r * (T_ * DD2);

    float v1[T_];
#pragma unroll
    for (int ti = 0; ti < T_; ti++) v1[ti] = xrow[ti*DD2 + dl];

    float acc[T_];
#pragma unroll
    for (int to = 0; to < T_; to++) acc[to] = bsh[to];

#pragma unroll
    for (int ti = 0; ti < T_; ti++) {
        float v0 = __shfl_up_sync(0xffffffffu, v1[ti], 1);
        float v2 = __shfl_down_sync(0xffffffffu, v1[ti], 1);
        if (lane == 0)  v0 = (d > 0) ? xrow[ti*DD2 + d - 1] : 0.f;
        if (lane == 31) v2 = (d < DD2 - 1) ? xrow[ti*DD2 + d + 1] : 0.f;
        if (d >= DD2 - 1) v2 = 0.f;
#pragma unroll
        for (int to = 0; to < T_; to++) {
            const float* wp = &w[(to*T_ + ti)*3];
            acc[to] += v0*wp[0] + v1[ti]*wp[1] + v2*wp[2];
        }
    }
    if (d < DD2) {
        long obase = (long)r * (T_ * DD2) + d;
#pragma unroll
        for (int to = 0; to < T_; to++)
            g_xca[obase + to*DD2] = __float2half(siluf(acc[to]));
    }
}

// ---------------- s[token] = dot(BC[:,0:128], BC[:,128:256]) ----------------
__global__ void sdot_kernel()
{
    int gwarp = (blockIdx.x * blockDim.x + threadIdx.x) >> 5;
    int lane  = threadIdx.x & 31;
    if (gwarp >= MTOK) return;
    const float* row = g_BC + (long)gwarp * 256;
    float4 a = *(const float4*)(row + lane * 4);
    float4 b = *(const float4*)(row + 128 + lane * 4);
    float acc = a.x*b.x + a.y*b.y + a.z*b.z + a.w*b.w;
#pragma unroll
    for (int o = 16; o; o >>= 1) acc += __shfl_xor_sync(0xffffffffu, acc, o);
    if (!lane) g_s[gwarp] = acc;
}

// ---------------- head ----------------
__global__ void out_kernel(const float* __restrict__ Wout, const float* __restrict__ bout,
                           float* __restrict__ out)
{
    int rn   = blockIdx.x;
    int wj   = threadIdx.x >> 5;
    int lane = threadIdx.x & 31;
    const float* row = g_h + (long)rn * (T_ * DM);
    float acc = 0.f;
    for (int k = lane; k < T_ * DM; k += 32) acc += row[k] * Wout[k*12 + wj];
#pragma unroll
    for (int o = 16; o; o >>= 1) acc += __shfl_xor_sync(0xffffffffu, acc, o);
    if (!lane) {
        int n = rn % NN_, b = rn / NN_;
        out[((long)b * 12 + wj) * NN_ + n] = acc + bout[wj];
    }
}

// =============================================================================
extern "C" void kernel_launch(void* const* d_in, const int* in_sizes, int n_in,
                              void* d_out, int out_size)
{
    (void)in_sizes; (void)n_in; (void)out_size;
    const float* x        = (const float*)d_in[0];
    const float* W_in     = (const float*)d_in[1];
    const float* b_in     = (const float*)d_in[2];
    const float* tod      = (const float*)d_in[3];
    const float* dow      = (const float*)d_in[4];
    const float* adp      = (const float*)d_in[5];
    const float* norm_w   = (const float*)d_in[6];
    const float* inproj_w = (const float*)d_in[7];
    const float* inproj_b = (const float*)d_in[8];
    const float* conv_w   = (const float*)d_in[9];
    const float* conv_b   = (const float*)d_in[10];
    const float* convlin_w= (const float*)d_in[11];
    const float* convlin_b= (const float*)d_in[12];
    const float* fc1_w    = (const float*)d_in[13];
    const float* fc1_b    = (const float*)d_in[14];
    const float* fc2_w    = (const float*)d_in[15];
    const float* fc2_b    = (const float*)d_in[16];
    const float* fc3_w    = (const float*)d_in[17];
    const float* fc3_b    = (const float*)d_in[18];
    /* d_in[19] = A_ssm unused (h0 == 0) */
    const float* D_w      = (const float*)d_in[20];
    const float* D_b      = (const float*)d_in[21];
    const float* outproj_w= (const float*)d_in[22];
    const float* outproj_b= (const float*)d_in[23];
    const float* W_out    = (const float*)d_in[24];
    const float* b_out    = (const float*)d_in[25];
    float* out = (float*)d_out;

    cudaFuncSetAttribute(mma_gemm<0>, cudaFuncAttributeMaxDynamicSharedMemorySize, SM_TOTAL);
    cudaFuncSetAttribute(mma_gemm<3>, cudaFuncAttributeMaxDynamicSharedMemorySize, SM_TOTAL);
    cudaFuncSetAttribute(mma_gemm<4>, cudaFuncAttributeMaxDynamicSharedMemorySize, SM_TOTAL);
    cudaFuncSetAttribute(mma_gemm<5>, cudaFuncAttributeMaxDynamicSharedMemorySize, SM_TOTAL);

    void* p;
#define SYM(sym, var, ty) cudaGetSymbolAddress(&p, sym); ty* var = (ty*)p;
    SYM(g_xp,    xp_p,   float)
    SYM(g_BC,    BC_p,   float)
    SYM(g_z,     z_p,    float)
    SYM(g_b23,   b23_p,  float)
    SYM(g_bipdw, bipdw_p,float)
    SYM(g_h,     h_p,    float)
    SYM(g_xn,    xn_p,   __half)
    SYM(g_xca,   xca_p,  __half)
    SYM(g_xco,   xco_p,  __half)
    SYM(g_cb,    cb_p,   __half)
    SYM(g_wipdw, wpd_p,  __half)
    SYM(g_wcl,   wcl_p,  __half)
    SYM(g_w23,   w23_p,  __half)
    SYM(g_wf1,   wf1_p,  __half)
    SYM(g_wop,   wop_p,  __half)
#undef SYM

    // ---- weight prep (3 launches) ----
    wprep_ipdw<<<(NL*2*DD2*DM + 255)/256, 256>>>(inproj_w, D_w);
    wprep_rest<<<(NL*SEG_ALL + 255)/256, 256>>>(convlin_w, fc2_w, fc3_w, fc1_w, outproj_w);
    pack_all<<<(NL*2*DD2 + NL*256 + 255)/256, 256>>>(inproj_b, D_b, fc2_b, fc3_b);

    // ---- embedding ----
    {
        long tot = (long)MTOK * DM;
        embed_kernel<<<(int)((tot + 255)/256), 256>>>(x, W_in, b_in, tod, dow, adp);
    }

    for (int i = 0; i < NL; i++) {
        rmsnorm_kernel<<<(MTOK*32 + 255)/256, 256>>>(norm_w + i*DM);

        // fused inproj|D_w : xn(152) -> xp(f32) & z(f32 silu), N=608
        mma_gemm<5><<<dim3(5, MTILES), 256, SM_TOTAL>>>(xn_p,
            wpd_p + (long)i*2*DD2*DM, bipdw_p + (long)i*2*DD2,
            xp_p, z_p, nullptr, MTOK, DM, 2*DD2, DD2);

        conv_silu_kernel<<<(ROWS*DCHUNKS*32 + 255)/256, 256>>>(conv_w + i*T_*T_*3, conv_b + i*T_);

        // convlin: xca(304) -> xco fp16(304)
        mma_gemm<3><<<dim3(3, MTILES), 256, SM_TOTAL>>>(xca_p,
            wcl_p + (long)i*DD2*DD2, convlin_b + i*DD2,
            nullptr, nullptr, xco_p, MTOK, DD2, DD2, DD2);

        // fc2|fc3 fused: xco(304) -> BC(256) f32
        mma_gemm<0><<<dim3(2, MTILES), 256, SM_TOTAL>>>(xco_p,
            w23_p + (long)i*256*DD2, b23_p + i*256,
            BC_p, nullptr, nullptr, MTOK, DD2, 256, 256);

        sdot_kernel<<<(MTOK*32 + 255)/256, 256>>>();

        // fc1 + combine fused: -> cb fp16(304)
        mma_gemm<4><<<dim3(3, MTILES), 256, SM_TOTAL>>>(xco_p,
            wf1_p + (long)i*DD2*DD2, fc1_b + i*DD2,
            nullptr, nullptr, cb_p, MTOK, DD2, DD2, DD2);

        // outproj: cb(304) -> h(152) f32
        mma_gemm<0><<<dim3(2, MTILES), 256, SM_TOTAL>>>(cb_p,
            wop_p + (long)i*DM*DD2, outproj_b + i*DM,
            h_p, nullptr, nullptr, MTOK, DD2, DM, DM);
    }

    out_kernel<<<ROWS, 384>>>(W_out, b_out, out);
}

// round 8
// speedup vs baseline: 2.7199x; 1.0687x over previous
#include <cuda_runtime.h>
#include <cuda_fp16.h>
#include <math.h>
#include <stdint.h>

#define B_    8
#define T_    12
#define NN_   883
#define DM    152
#define DD2   304
#define SSZ   128
#define NL    3
#define STEPS 288
#define ROWS  (B_*NN_)          /* 7064  */
#define MTOK  (ROWS*T_)         /* 84768 */
#define MTILES ((MTOK+127)/128) /* 663   */

// ---------------- scratch (device globals; no allocs allowed) ----------------
__device__ float g_h [MTOK*DM];
__device__ float g_s [MTOK];

__device__ __half g_xn [MTOK*DM];
__device__ __half g_xp [MTOK*DD2];
__device__ __half g_z  [MTOK*DD2];
__device__ __half g_xca[MTOK*DD2];
__device__ __half g_xco[MTOK*DD2];
__device__ __half g_cb [MTOK*DD2];

// transposed fp16 weights: [N rows, K cols]
__device__ __half g_wipdw[NL*2*DD2*DM];   /* 608 x 152 */
__device__ __half g_wcl  [NL*DD2*DD2];
__device__ __half g_w23  [NL*256*DD2];    /* interleaved: row 2j=fc2_j, 2j+1=fc3_j */
__device__ __half g_wf1  [NL*DD2*DD2];
__device__ __half g_wop  [NL*DM*DD2];
__device__ float  g_b23  [NL*256];
__device__ float  g_bipdw[NL*2*DD2];

__device__ __forceinline__ float siluf(float v)     { return v / (1.f + expf(-v)); }
__device__ __forceinline__ float softplusf(float v) { return (v > 20.f) ? v : log1pf(expf(v)); }

__device__ __forceinline__ uint32_t sm2u32(const void* p) {
    uint32_t a;
    asm("{ .reg .u64 t; cvta.to.shared.u64 t, %1; cvt.u32.u64 %0, t; }" : "=r"(a) : "l"(p));
    return a;
}
#define SWZ(o) ((uint32_t)(o) ^ ((((uint32_t)(o)) >> 3) & 0x70u))

__device__ __forceinline__ void ldsm4(uint32_t* r, uint32_t addr) {
    asm volatile("ldmatrix.sync.aligned.m8n8.x4.shared.b16 {%0,%1,%2,%3}, [%4];"
                 : "=r"(r[0]), "=r"(r[1]), "=r"(r[2]), "=r"(r[3]) : "r"(addr));
}
__device__ __forceinline__ void mma16816(float* c, const uint32_t* a, const uint32_t* b) {
    asm volatile("mma.sync.aligned.m16n8k16.row.col.f32.f16.f16.f32 "
                 "{%0,%1,%2,%3}, {%4,%5,%6,%7}, {%8,%9}, {%0,%1,%2,%3};"
                 : "+f"(c[0]), "+f"(c[1]), "+f"(c[2]), "+f"(c[3])
                 : "r"(a[0]), "r"(a[1]), "r"(a[2]), "r"(a[3]), "r"(b[0]), "r"(b[1]));
}
__device__ __forceinline__ void cpa16(uint32_t dst, const void* src, uint32_t sz) {
    asm volatile("cp.async.cg.shared.global [%0], [%1], 16, %2;"
                 :: "r"(dst), "l"(src), "r"(sz) : "memory");
}
__device__ __forceinline__ void cp_commit() {
    asm volatile("cp.async.commit_group;" ::: "memory");
}
template<int N>
__device__ __forceinline__ void cp_wait() {
    asm volatile("cp.async.wait_group %0;" :: "n"(N) : "memory");
}

// ---------------- fused epilogue -------------------------------------------
// EPI: 0 bias->f32 | 3 bias->fp16 | 4 fc1+combine->fp16
//      5 dual fp16: col<DD2 -> xp ; col>=DD2 -> silu -> z
//      6 handled inline in the GEMM (BC pair-product -> atomic s)
template<int EPI>
__device__ __forceinline__ void epi2(int m, int col, int ldc, float v0, float v1,
    const float* __restrict__ bias, float* Cf, __half* Ch, __half* Ch2)
{
    v0 += bias[col]; v1 += bias[col + 1];
    if (EPI == 4) {
        float sv = g_s[m];
        size_t off = (size_t)m * DD2 + col;
        float xc0 = __half2float(g_xco[off]);
        float xc1 = __half2float(g_xco[off + 1]);
        v0 = siluf(xc0 * softplusf(v0) * sv) * __half2float(g_z[off]);
        v1 = siluf(xc1 * softplusf(v1) * sv) * __half2float(g_z[off + 1]);
    }
    if (EPI == 0) {
        *(float2*)(Cf + (size_t)m * ldc + col) = make_float2(v0, v1);
    } else if (EPI == 5) {
        if (col < DD2) {
            *(__half2*)(Ch + (size_t)m * DD2 + col) =
                __halves2half2(__float2half(v0), __float2half(v1));
        } else {
            *(__half2*)(Ch2 + (size_t)m * DD2 + (col - DD2)) =
                __halves2half2(__float2half(siluf(v0)), __float2half(siluf(v1)));
        }
    } else {
        *(__half2*)(Ch + (size_t)m * ldc + col) =
            __halves2half2(__float2half(v0), __float2half(v1));
    }
}

// ---------------- GEMM: C[M,Nw] = epi(A[M,K] @ B[Nw,K]^T + bias) -------------
// CTA tile 128(M) x 128(N), K-chunk 64, 2-stage cp.async, 2 CTAs/SM.
#define STA 0
#define STB 16384
#define STG_SZ 32768
#define SM_TOTAL (2*STG_SZ)

template<int EPI>
__global__ void __launch_bounds__(256, 2)
mma_gemm(const __half* __restrict__ A, const __half* __restrict__ B,
         const float* __restrict__ bias,
         float* Cf, __half* Ch, __half* Ch2,
         int M, int K, int Nw, int ldc)
{
    extern __shared__ char smem[];
    const uint32_t sb = sm2u32(smem);
    const int tid  = threadIdx.x;
    const int lane = tid & 31;
    const int wid  = tid >> 5;
    const int wm   = wid & 3;      // 0..3 (M)
    const int wn   = wid >> 2;     // 0..1 (N)
    const int m0   = blockIdx.y * 128;
    const int n0   = blockIdx.x * 128;

    float acc[2][8][4];
#pragma unroll
    for (int i = 0; i < 2; i++)
#pragma unroll
        for (int j = 0; j < 8; j++)
#pragma unroll
            for (int q = 0; q < 4; q++) acc[i][j][q] = 0.f;

    const int KC = (K + 63) >> 6;

    auto load_stage = [&](int stg, int k0) {
        uint32_t base = sb + stg * STG_SZ;
#pragma unroll
        for (int i = 0; i < 4; i++) {          // A: 128 rows x 64 k
            int idx = tid + i * 256;
            int r = idx >> 3, u = idx & 7;
            int gm = m0 + r, gk = k0 + u * 8;
            bool ok = (gm < M) && (gk < K);
            size_t go = (size_t)(ok ? gm : 0) * K + (ok ? gk : 0);
            cpa16(base + STA + SWZ(r * 128 + u * 16), A + go, ok ? 16u : 0u);
        }
#pragma unroll
        for (int i = 0; i < 4; i++) {          // B: 128 rows x 64 k
            int idx = tid + i * 256;
            int r = idx >> 3, u = idx & 7;
            int gn = n0 + r, gk = k0 + u * 8;
            bool ok = (gn < Nw) && (gk < K);
            size_t go = (size_t)(ok ? gn : 0) * K + (ok ? gk : 0);
            cpa16(base + STB + SWZ(r * 128 + u * 16), B + go, ok ? 16u : 0u);
        }
    };

    load_stage(0, 0);
    cp_commit();

    for (int c = 0; c < KC; c++) {
        if (c + 1 < KC) {
            load_stage((c + 1) & 1, (c + 1) << 6);
            cp_commit();
            cp_wait<1>();
        } else {
            cp_wait<0>();
        }
        __syncthreads();

        const uint32_t base = sb + (c & 1) * STG_SZ;
#pragma unroll
        for (int ks = 0; ks < 4; ks++) {
            const int kb = ks * 16;
            uint32_t ah[2][4];
#pragma unroll
            for (int mt = 0; mt < 2; mt++) {
                int row = wm * 32 + mt * 16 + (lane & 15);
                ldsm4(ah[mt], base + STA + SWZ(row * 128 + (kb + (lane >> 4) * 8) * 2));
            }
            const int q = lane >> 3;
            const int rowo = (q >> 1) * 8 + (lane & 7);
            const int ko   = (q & 1) * 8;
            uint32_t bf[8][2];
#pragma unroll
            for (int p = 0; p < 4; p++) {
                int row = wn * 64 + p * 16 + rowo;
                uint32_t r4[4];
                ldsm4(r4, base + STB + SWZ(row * 128 + (kb + ko) * 2));
                bf[2*p][0] = r4[0]; bf[2*p][1] = r4[1];
                bf[2*p+1][0] = r4[2]; bf[2*p+1][1] = r4[3];
            }
#pragma unroll
            for (int mt = 0; mt < 2; mt++)
#pragma unroll
                for (int nt = 0; nt < 8; nt++)
                    mma16816(acc[mt][nt], ah[mt], bf[nt]);
        }
        __syncthreads();
    }

    // ---- epilogue ----
    if (EPI == 6) {
        // BC pair-product: cols hold (Bm_j, Cm_j) pairs; accumulate -> atomic s
#pragma unroll
        for (int mt = 0; mt < 2; mt++) {
            int r0 = m0 + wm * 32 + mt * 16 + (lane >> 2);
            int r1 = r0 + 8;
            float s0 = 0.f, s1 = 0.f;
#pragma unroll
            for (int nt = 0; nt < 8; nt++) {
                int col = n0 + wn * 64 + nt * 8 + (lane & 3) * 2;
                float b0 = bias[col], b1 = bias[col + 1];
                s0 += (acc[mt][nt][0] + b0) * (acc[mt][nt][1] + b1);
                s1 += (acc[mt][nt][2] + b0) * (acc[mt][nt][3] + b1);
            }
            if (r0 < M) atomicAdd(&g_s[r0], s0);
            if (r1 < M) atomicAdd(&g_s[r1], s1);
        }
    } else {
#pragma unroll
        for (int mt = 0; mt < 2; mt++) {
            int r0 = m0 + wm * 32 + mt * 16 + (lane >> 2);
            int r1 = r0 + 8;
#pragma unroll
            for (int nt = 0; nt < 8; nt++) {
                int col = n0 + wn * 64 + nt * 8 + (lane & 3) * 2;
                if (col < Nw) {
                    if (r0 < M) epi2<EPI>(r0, col, ldc, acc[mt][nt][0], acc[mt][nt][1], bias, Cf, Ch, Ch2);
                    if (r1 < M) epi2<EPI>(r1, col, ldc, acc[mt][nt][2], acc[mt][nt][3], bias, Cf, Ch, Ch2);
                }
            }
        }
    }
}

// ---------------- weight prep (3 launches total) ------------------------------
__global__ void wprep_ipdw(const float* __restrict__ inw, const float* __restrict__ dww)
{
    int idx = blockIdx.x * blockDim.x + threadIdx.x;
    const int PER = 2 * DD2 * DM;
    if (idx >= NL * PER) return;
    int l = idx / PER, q = idx % PER;
    int n = q / DM, k = q % DM;
    float v = (n < DD2) ? inw[(size_t)l*DM*DD2 + k*DD2 + n]
                        : dww[(size_t)l*DM*DD2 + k*DD2 + (n - DD2)];
    g_wipdw[idx] = __float2half(v);
}

#define SEG_CL  (DD2*DD2)
#define SEG_23  (256*DD2)
#define SEG_F1  (DD2*DD2)
#define SEG_OP  (DM*DD2)
#define SEG_ALL (SEG_CL+SEG_23+SEG_F1+SEG_OP)
__global__ void wprep_rest(const float* __restrict__ cl, const float* __restrict__ f2,
                           const float* __restrict__ f3, const float* __restrict__ f1,
                           const float* __restrict__ op)
{
    int idx = blockIdx.x * blockDim.x + threadIdx.x;
    if (idx >= NL * SEG_ALL) return;
    int l = idx / SEG_ALL, r = idx % SEG_ALL;
    if (r < SEG_CL) {
        int n = r / DD2, k = r % DD2;
        g_wcl[(long)l*SEG_CL + r] = __float2half(cl[(size_t)l*SEG_CL + (size_t)k*DD2 + n]);
    } else if (r < SEG_CL + SEG_23) {
        int q = r - SEG_CL;
        int n = q / DD2, k = q % DD2;       // n: interleaved output col, k: input dim
        int j = n >> 1;
        float v = (n & 1) ? f3[(size_t)l*DD2*SSZ + (size_t)k*SSZ + j]
                          : f2[(size_t)l*DD2*SSZ + (size_t)k*SSZ + j];
        g_w23[(long)l*SEG_23 + q] = __float2half(v);
    } else if (r < SEG_CL + SEG_23 + SEG_F1) {
        int q = r - SEG_CL - SEG_23;
        int n = q / DD2, k = q % DD2;
        g_wf1[(long)l*SEG_F1 + q] = __float2half(f1[(size_t)l*SEG_F1 + (size_t)k*DD2 + n]);
    } else {
        int q = r - SEG_CL - SEG_23 - SEG_F1;
        int n = q / DD2, k = q % DD2;
        g_wop[(long)l*SEG_OP + q] = __float2half(op[(size_t)l*SEG_OP + (size_t)k*DM + n]);
    }
}

__global__ void pack_all(const float* __restrict__ inb, const float* __restrict__ db,
                         const float* __restrict__ f2b, const float* __restrict__ f3b)
{
    int i = blockIdx.x * blockDim.x + threadIdx.x;
    const int N1 = NL * 2 * DD2;
    if (i < N1) {
        int l = i / (2*DD2), j = i % (2*DD2);
        g_bipdw[i] = (j < DD2) ? inb[l*DD2 + j] : db[l*DD2 + (j - DD2)];
    } else if (i < N1 + NL*256) {
        int q = i - N1;
        int l = q / 256, j = q % 256;
        g_b23[q] = (j & 1) ? f3b[l*SSZ + (j >> 1)] : f2b[l*SSZ + (j >> 1)];
    }
}

// ---------------- embedding ----------------
__global__ void embed_kernel(const float* __restrict__ x, const float* __restrict__ W_in,
                             const float* __restrict__ b_in, const float* __restrict__ tod,
                             const float* __restrict__ dow, const float* __restrict__ adp)
{
    long idx = blockIdx.x * (long)blockDim.x + threadIdx.x;
    if (idx >= (long)MTOK * DM) return;
    int  c      = (int)(idx % DM);
    long tokidx = idx / DM;
    int  t      = (int)(tokidx % T_);
    long rn     = tokidx / T_;
    int  n      = (int)(rn % NN_);
    int  b      = (int)(rn / NN_);
    const float* xe = x + (((long)(b * T_ + t) * NN_ + n) * 3);
    float v;
    if (c < 24) {
        v = b_in[c] + xe[0]*W_in[c] + xe[1]*W_in[24+c] + xe[2]*W_in[48+c];
    } else if (c < 48) {
        int ti = (int)(xe[1] * (float)STEPS);
        ti = min(max(ti, 0), STEPS - 1);
        v = tod[ti*24 + (c-24)];
    } else if (c < 72) {
        int di = (int)xe[2];
        di = min(max(di, 0), 6);
        v = dow[di*24 + (c-48)];
    } else {
        v = adp[((long)t * NN_ + n) * 80 + (c - 72)];
    }
    g_h[idx] = v;
}

// ---------------- rmsnorm -> fp16 ; also zeroes g_s --------------------------
__global__ void rmsnorm_kernel(const float* __restrict__ w)
{
    int gwarp = (blockIdx.x * blockDim.x + threadIdx.x) >> 5;
    int lane  = threadIdx.x & 31;
    if (gwarp >= MTOK) return;
    const float* row = g_h + (long)gwarp * DM;
    float ss = 0.f;
    for (int c = lane; c < DM; c += 32) { float v = row[c]; ss += v * v; }
#pragma unroll
    for (int o = 16; o; o >>= 1) ss += __shfl_xor_sync(0xffffffffu, ss, o);
    float scale = rsqrtf(ss / (float)DM + 1e-5f);
    long base = (long)gwarp * DM;
    for (int c = lane; c < DM; c += 32)
        g_xn[base + c] = __float2half(row[c] * scale * w[c]);
    if (!lane) g_s[gwarp] = 0.f;
}

// ---------------- conv over T + silu -> fp16 (warp-aligned shfl) -------------
#define DCHUNKS 10
__global__ void conv_silu_kernel(const float* __restrict__ cw, const float* __restrict__ cb)
{
    __shared__ float w[T_*T_*3];
    __shared__ float bsh[T_];
    for (int i = threadIdx.x; i < T_*T_*3; i += blockDim.x) w[i] = cw[i];
    for (int i = threadIdx.x; i < T_;      i += blockDim.x) bsh[i] = cb[i];
    __syncthreads();

    int gw = (int)((blockIdx.x * (long)blockDim.x + threadIdx.x) >> 5);
    if (gw >= ROWS * DCHUNKS) return;
    int lane = threadIdx.x & 31;
    int r  = gw / DCHUNKS;
    int dc = gw % DCHUNKS;
    int d  = dc * 32 + lane;
    int dl = min(d, DD2 - 1);
    const __half* xrow = g_xp + (long)r * (T_ * DD2);

    float v1[T_];
#pragma unroll
    for (int ti = 0; ti < T_; ti++) v1[ti] = __half2float(xrow[ti*DD2 + dl]);

    float acc[T_];
#pragma unroll
    for (int to = 0; to < T_; to++) acc[to] = bsh[to];

#pragma unroll
    for (int ti = 0; ti < T_; ti++) {
        float v0 = __shfl_up_sync(0xffffffffu, v1[ti], 1);
        float v2 = __shfl_down_sync(0xffffffffu, v1[ti], 1);
        if (lane == 0)  v0 = (d > 0) ? __half2float(xrow[ti*DD2 + d - 1]) : 0.f;
        if (lane == 31) v2 = (d < DD2 - 1) ? __half2float(xrow[ti*DD2 + d + 1]) : 0.f;
        if (d >= DD2 - 1) v2 = 0.f;
#pragma unroll
        for (int to = 0; to < T_; to++) {
            const float* wp = &w[(to*T_ + ti)*3];
            acc[to] += v0*wp[0] + v1[ti]*wp[1] + v2*wp[2];
        }
    }
    if (d < DD2) {
        long obase = (long)r * (T_ * DD2) + d;
#pragma unroll
        for (int to = 0; to < T_; to++)
            g_xca[obase + to*DD2] = __float2half(siluf(acc[to]));
    }
}

// ---------------- head ----------------
__global__ void out_kernel(const float* __restrict__ Wout, const float* __restrict__ bout,
                           float* __restrict__ out)
{
    int rn   = blockIdx.x;
    int wj   = threadIdx.x >> 5;
    int lane = threadIdx.x & 31;
    const float* row = g_h + (long)rn * (T_ * DM);
    float acc = 0.f;
    for (int k = lane; k < T_ * DM; k += 32) acc += row[k] * Wout[k*12 + wj];
#pragma unroll
    for (int o = 16; o; o >>= 1) acc += __shfl_xor_sync(0xffffffffu, acc, o);
    if (!lane) {
        int n = rn % NN_, b = rn / NN_;
        out[((long)b * 12 + wj) * NN_ + n] = acc + bout[wj];
    }
}

// =============================================================================
extern "C" void kernel_launch(void* const* d_in, const int* in_sizes, int n_in,
                              void* d_out, int out_size)
{
    (void)in_sizes; (void)n_in; (void)out_size;
    const float* x        = (const float*)d_in[0];
    const float* W_in     = (const float*)d_in[1];
    const float* b_in     = (const float*)d_in[2];
    const float* tod      = (const float*)d_in[3];
    const float* dow      = (const float*)d_in[4];
    const float* adp      = (const float*)d_in[5];
    const float* norm_w   = (const float*)d_in[6];
    const float* inproj_w = (const float*)d_in[7];
    const float* inproj_b = (const float*)d_in[8];
    const float* conv_w   = (const float*)d_in[9];
    const float* conv_b   = (const float*)d_in[10];
    const float* convlin_w= (const float*)d_in[11];
    const float* convlin_b= (const float*)d_in[12];
    const float* fc1_w    = (const float*)d_in[13];
    const float* fc1_b    = (const float*)d_in[14];
    const float* fc2_w    = (const float*)d_in[15];
    const float* fc2_b    = (const float*)d_in[16];
    const float* fc3_w    = (const float*)d_in[17];
    const float* fc3_b    = (const float*)d_in[18];
    /* d_in[19] = A_ssm unused (h0 == 0) */
    const float* D_w      = (const float*)d_in[20];
    const float* D_b      = (const float*)d_in[21];
    const float* outproj_w= (const float*)d_in[22];
    const float* outproj_b= (const float*)d_in[23];
    const float* W_out    = (const float*)d_in[24];
    const float* b_out    = (const float*)d_in[25];
    float* out = (float*)d_out;

    cudaFuncSetAttribute(mma_gemm<0>, cudaFuncAttributeMaxDynamicSharedMemorySize, SM_TOTAL);
    cudaFuncSetAttribute(mma_gemm<3>, cudaFuncAttributeMaxDynamicSharedMemorySize, SM_TOTAL);
    cudaFuncSetAttribute(mma_gemm<4>, cudaFuncAttributeMaxDynamicSharedMemorySize, SM_TOTAL);
    cudaFuncSetAttribute(mma_gemm<5>, cudaFuncAttributeMaxDynamicSharedMemorySize, SM_TOTAL);
    cudaFuncSetAttribute(mma_gemm<6>, cudaFuncAttributeMaxDynamicSharedMemorySize, SM_TOTAL);

    void* p;
#define SYM(sym, var, ty) cudaGetSymbolAddress(&p, sym); ty* var = (ty*)p;
    SYM(g_b23,   b23_p,  float)
    SYM(g_bipdw, bipdw_p,float)
    SYM(g_h,     h_p,    float)
    SYM(g_xn,    xn_p,   __half)
    SYM(g_xp,    xp_p,   __half)
    SYM(g_z,     z_p,    __half)
    SYM(g_xca,   xca_p,  __half)
    SYM(g_xco,   xco_p,  __half)
    SYM(g_cb,    cb_p,   __half)
    SYM(g_wipdw, wpd_p,  __half)
    SYM(g_wcl,   wcl_p,  __half)
    SYM(g_w23,   w23_p,  __half)
    SYM(g_wf1,   wf1_p,  __half)
    SYM(g_wop,   wop_p,  __half)
#undef SYM

    // ---- weight prep (3 launches) ----
    wprep_ipdw<<<(NL*2*DD2*DM + 255)/256, 256>>>(inproj_w, D_w);
    wprep_rest<<<(NL*SEG_ALL + 255)/256, 256>>>(convlin_w, fc2_w, fc3_w, fc1_w, outproj_w);
    pack_all<<<(NL*2*DD2 + NL*256 + 255)/256, 256>>>(inproj_b, D_b, fc2_b, fc3_b);

    // ---- embedding ----
    {
        long tot = (long)MTOK * DM;
        embed_kernel<<<(int)((tot + 255)/256), 256>>>(x, W_in, b_in, tod, dow, adp);
    }

    for (int i = 0; i < NL; i++) {
        rmsnorm_kernel<<<(MTOK*32 + 255)/256, 256>>>(norm_w + i*DM);

        // fused inproj|D_w : xn(152) -> xp(fp16) & z(fp16 silu), N=608
        mma_gemm<5><<<dim3(5, MTILES), 256, SM_TOTAL>>>(xn_p,
            wpd_p + (long)i*2*DD2*DM, bipdw_p + (long)i*2*DD2,
            nullptr, xp_p, z_p, MTOK, DM, 2*DD2, DD2);

        conv_silu_kernel<<<(ROWS*DCHUNKS*32 + 255)/256, 256>>>(conv_w + i*T_*T_*3, conv_b + i*T_);

        // convlin: xca(304) -> xco fp16(304)
        mma_gemm<3><<<dim3(3, MTILES), 256, SM_TOTAL>>>(xca_p,
            wcl_p + (long)i*DD2*DD2, convlin_b + i*DD2,
            nullptr, xco_p, nullptr, MTOK, DD2, DD2, DD2);

        // fc2|fc3 interleaved: epilogue computes s via pair products + atomics
        mma_gemm<6><<<dim3(2, MTILES), 256, SM_TOTAL>>>(xco_p,
            w23_p + (long)i*256*DD2, b23_p + i*256,
            nullptr, nullptr, nullptr, MTOK, DD2, 256, 256);

        // fc1 + combine fused: -> cb fp16(304)
        mma_gemm<4><<<dim3(3, MTILES), 256, SM_TOTAL>>>(xco_p,
            wf1_p + (long)i*DD2*DD2, fc1_b + i*DD2,
            nullptr, cb_p, nullptr, MTOK, DD2, DD2, DD2);

        // outproj: cb(304) -> h(152) f32
        mma_gemm<0><<<dim3(2, MTILES), 256, SM_TOTAL>>>(cb_p,
            wop_p + (long)i*DM*DD2, outproj_b + i*DM,
            h_p, nullptr, nullptr, MTOK, DD2, DM, DM);
    }

    out_kernel<<<ROWS, 384>>>(W_out, b_out, out);
}